// round 2
// baseline (speedup 1.0000x reference)
#include <cuda_runtime.h>
#include <math.h>

#define B_  2
#define N_  2048
#define D_  1024
#define H_  16
#define HD_ 64

// Scratch (allocation-free rule: __device__ globals)
__device__ float g_q[B_*H_*N_*HD_];
__device__ float g_k[B_*H_*N_*HD_];
__device__ float g_v[B_*H_*N_*HD_];
__device__ float g_attn[B_*N_*D_];
__device__ float g_cos[N_*(HD_/2)];
__device__ float g_sin[N_*(HD_/2)];

// ---------------------------------------------------------------------------
// RoPE table: angle computed like the reference (fp32 inv_freq * fp32 pos),
// trig in double for accuracy.
// ---------------------------------------------------------------------------
__global__ void rope_table_kernel() {
    int idx = blockIdx.x * blockDim.x + threadIdx.x;   // N_*32 = 65536
    if (idx >= N_ * (HD_/2)) return;
    int n = idx >> 5;
    int p = idx & 31;                                   // pair index -> dims (2p, 2p+1)
    float invf = (float)pow(10000.0, -(double)(2 * p) / (double)HD_);
    float ang_f = (float)n * invf;                      // fp32 like reference
    double ang = (double)ang_f;
    g_cos[idx] = (float)cos(ang);
    g_sin[idx] = (float)sin(ang);
}

// ---------------------------------------------------------------------------
// Tiled fp32 GEMM: C[M, NC] = A[M,1024] @ W[NC,1024]^T + bias
// BM=BN=64, BK=16, 256 threads, 4x4 register tile per thread.
// QKV=true : epilogue splits q/k/v, applies RoPE to q,k, scatters to [B,H,N,HD]
// QKV=false: A is g_attn, epilogue writes C (= d_out) directly.
// ---------------------------------------------------------------------------
template<bool QKV>
__global__ void __launch_bounds__(256) gemm64_kernel(
    const float* __restrict__ A,        // QKV: x [4096,1024]; proj: ignored
    const float* __restrict__ W,        // [NC,1024] row-major
    const float* __restrict__ bias,     // [NC]
    float* __restrict__ O0,             // QKV: g_q ; proj: d_out
    float* __restrict__ O1,             // QKV: g_k
    float* __restrict__ O2)             // QKV: g_v
{
    __shared__ float As[16][64];        // [k][m]
    __shared__ float Bs[16][64];        // [k][n]
    const int K = 1024;

    const float* Abase = QKV ? A : (const float*)g_attn;

    int tid = threadIdx.x;
    int tx = tid & 15, ty = tid >> 4;
    int m0 = blockIdx.x * 64, n0 = blockIdx.y * 64;
    int lm = tid >> 2, lk = (tid & 3) << 2;

    const float* Ap = Abase + (size_t)(m0 + lm) * K + lk;
    const float* Wp = W     + (size_t)(n0 + lm) * K + lk;

    float acc[4][4] = {};

    for (int k0 = 0; k0 < K; k0 += 16) {
        float4 av = *(const float4*)(Ap + k0);
        float4 bv = *(const float4*)(Wp + k0);
        As[lk+0][lm] = av.x; As[lk+1][lm] = av.y;
        As[lk+2][lm] = av.z; As[lk+3][lm] = av.w;
        Bs[lk+0][lm] = bv.x; Bs[lk+1][lm] = bv.y;
        Bs[lk+2][lm] = bv.z; Bs[lk+3][lm] = bv.w;
        __syncthreads();
#pragma unroll
        for (int k = 0; k < 16; k++) {
            float4 a = *(const float4*)&As[k][ty << 2];
            float4 b = *(const float4*)&Bs[k][tx << 2];
            float aa[4] = {a.x, a.y, a.z, a.w};
            float bb[4] = {b.x, b.y, b.z, b.w};
#pragma unroll
            for (int i = 0; i < 4; i++)
#pragma unroll
                for (int j = 0; j < 4; j++)
                    acc[i][j] += aa[i] * bb[j];
        }
        __syncthreads();
    }

    int nc0 = n0 + (tx << 2);
    float b0 = bias[nc0], b1 = bias[nc0+1], b2 = bias[nc0+2], b3 = bias[nc0+3];

    if (!QKV) {
#pragma unroll
        for (int i = 0; i < 4; i++) {
            int m = m0 + (ty << 2) + i;
            *(float4*)(O0 + (size_t)m * 1024 + nc0) =
                make_float4(acc[i][0]+b0, acc[i][1]+b1, acc[i][2]+b2, acc[i][3]+b3);
        }
    } else {
        int region = n0 >> 10;               // 0=q, 1=k, 2=v (tile never straddles)
        int h = (n0 & 1023) >> 6;            // head (tile never straddles heads)
        int hd0 = nc0 & 63;
#pragma unroll
        for (int i = 0; i < 4; i++) {
            int m = m0 + (ty << 2) + i;
            int bb_ = m >> 11;
            int n   = m & 2047;
            float v0 = acc[i][0]+b0, v1 = acc[i][1]+b1;
            float v2 = acc[i][2]+b2, v3 = acc[i][3]+b3;
            float* dst;
            if (region == 2) {
                dst = O2;
            } else {
                int p0 = hd0 >> 1, p1 = p0 + 1;
                float c0 = g_cos[n*32 + p0], s0 = g_sin[n*32 + p0];
                float c1 = g_cos[n*32 + p1], s1 = g_sin[n*32 + p1];
                float r0 = v0*c0 - v1*s0;
                float r1 = v1*c0 + v0*s0;
                float r2 = v2*c1 - v3*s1;
                float r3 = v3*c1 + v2*s1;
                v0 = r0; v1 = r1; v2 = r2; v3 = r3;
                dst = (region == 0) ? O0 : O1;
            }
            *(float4*)(dst + ((size_t)(bb_*H_ + h) * N_ + n) * HD_ + hd0) =
                make_float4(v0, v1, v2, v3);
        }
    }
}

// ---------------------------------------------------------------------------
// Causal flash attention, fp32. Block = (m_tile, b*h). 64x64 tiles.
// smem: Qt[d][row] 16KB + KP (Kt[d][col] reused as P[row][col]) 16KB + Vs 16KB.
// Tile fill: 64x64 floats = 16 floats/thread -> each thread loads 4x float4:
//   row = tid>>2, dims (tid&3)*16 .. +15.
// ---------------------------------------------------------------------------
__global__ void __launch_bounds__(256) flash_kernel(float* __restrict__ Og) {
    __shared__ float Qt[64][64];   // transposed Q tile [d][row], pre-scaled
    __shared__ float KP[64][64];   // Kt [d][col], then reused as P [row][col]
    __shared__ float Vs[64][64];   // V tile [col][d]

    int tid = threadIdx.x;
    int tx = tid & 15, ty = tid >> 4;
    int mt = blockIdx.x;
    int bh = blockIdx.y;
    int m0 = mt * 64;

    const float* Qb = g_q + (size_t)bh * N_ * HD_;
    const float* Kb = g_k + (size_t)bh * N_ * HD_;
    const float* Vb = g_v + (size_t)bh * N_ * HD_;

    int lr = tid >> 2;            // row within tile [0,64)
    int c0 = (tid & 3) << 4;      // starting dim, 16 dims per thread

    {
        const float sc = 0.125f;   // 1/sqrt(64)
        const float* qrow = Qb + (size_t)(m0 + lr) * HD_;
#pragma unroll
        for (int j = 0; j < 4; j++) {
            float4 q = *(const float4*)(qrow + c0 + 4*j);
            int d = c0 + 4*j;
            Qt[d+0][lr] = q.x * sc; Qt[d+1][lr] = q.y * sc;
            Qt[d+2][lr] = q.z * sc; Qt[d+3][lr] = q.w * sc;
        }
    }

    float o[4][4] = {};
    float mrow[4] = {-1e30f, -1e30f, -1e30f, -1e30f};
    float lrow[4] = {};
    int r0 = ty << 2;

    for (int nt = 0; nt <= mt; nt++) {
        int n0k = nt * 64;
        __syncthreads();           // prior iter done reading KP/Vs; covers Qt init
        {
            const float* krow = Kb + (size_t)(n0k + lr) * HD_;
            const float* vrow = Vb + (size_t)(n0k + lr) * HD_;
#pragma unroll
            for (int j = 0; j < 4; j++) {
                int d = c0 + 4*j;
                float4 kq = *(const float4*)(krow + d);
                KP[d+0][lr] = kq.x; KP[d+1][lr] = kq.y;
                KP[d+2][lr] = kq.z; KP[d+3][lr] = kq.w;
                *(float4*)&Vs[lr][d] = *(const float4*)(vrow + d);
            }
        }
        __syncthreads();

        // S = (Q*scale) @ K^T
        float s[4][4] = {};
#pragma unroll
        for (int d = 0; d < 64; d++) {
            float4 a = *(const float4*)&Qt[d][r0];
            float4 b = *(const float4*)&KP[d][tx << 2];
            float aa[4] = {a.x, a.y, a.z, a.w};
            float bb[4] = {b.x, b.y, b.z, b.w};
#pragma unroll
            for (int i = 0; i < 4; i++)
#pragma unroll
                for (int j = 0; j < 4; j++)
                    s[i][j] += aa[i] * bb[j];
        }

        if (nt == mt) {            // diagonal tile: causal mask
#pragma unroll
            for (int i = 0; i < 4; i++)
#pragma unroll
                for (int j = 0; j < 4; j++)
                    if (n0k + (tx << 2) + j > m0 + r0 + i) s[i][j] = -1e30f;
        }

        // online softmax (row groups = 16 lanes sharing ty; xor-shfl allreduce)
#pragma unroll
        for (int i = 0; i < 4; i++) {
            float mx = fmaxf(fmaxf(s[i][0], s[i][1]), fmaxf(s[i][2], s[i][3]));
#pragma unroll
            for (int off = 1; off < 16; off <<= 1)
                mx = fmaxf(mx, __shfl_xor_sync(0xffffffffu, mx, off));
            float mn = fmaxf(mrow[i], mx);
            float al = __expf(mrow[i] - mn);
            mrow[i] = mn;
            float rs = 0.f;
#pragma unroll
            for (int j = 0; j < 4; j++) {
                float p = __expf(s[i][j] - mn);
                s[i][j] = p;
                rs += p;
            }
#pragma unroll
            for (int off = 1; off < 16; off <<= 1)
                rs += __shfl_xor_sync(0xffffffffu, rs, off);
            lrow[i] = lrow[i] * al + rs;
#pragma unroll
            for (int j = 0; j < 4; j++) o[i][j] *= al;
        }

        __syncthreads();           // done reading KP as Kt
#pragma unroll
        for (int i = 0; i < 4; i++)
            *(float4*)&KP[r0 + i][tx << 2] =
                make_float4(s[i][0], s[i][1], s[i][2], s[i][3]);
        __syncthreads();

        // O += P @ V
#pragma unroll
        for (int c = 0; c < 64; c++) {
            float4 b = *(const float4*)&Vs[c][tx << 2];
            float bb[4] = {b.x, b.y, b.z, b.w};
            float a0 = KP[r0+0][c], a1 = KP[r0+1][c];
            float a2 = KP[r0+2][c], a3 = KP[r0+3][c];
#pragma unroll
            for (int j = 0; j < 4; j++) {
                o[0][j] += a0 * bb[j];
                o[1][j] += a1 * bb[j];
                o[2][j] += a2 * bb[j];
                o[3][j] += a3 * bb[j];
            }
        }
    }

    // epilogue: write [B, N, H*HD]
    int b_ = bh >> 4, h = bh & 15;
    int hd0 = tx << 2;
#pragma unroll
    for (int i = 0; i < 4; i++) {
        int qr = m0 + r0 + i;
        float inv = 1.f / lrow[i];
        *(float4*)(Og + ((size_t)(b_ * N_ + qr) * D_) + h * HD_ + hd0) =
            make_float4(o[i][0]*inv, o[i][1]*inv, o[i][2]*inv, o[i][3]*inv);
    }
}

// ---------------------------------------------------------------------------
extern "C" void kernel_launch(void* const* d_in, const int* in_sizes, int n_in,
                              void* d_out, int out_size)
{
    const float* x      = (const float*)d_in[0];
    const float* qkv_w  = (const float*)d_in[1];
    const float* qkv_b  = (const float*)d_in[2];
    const float* proj_w = (const float*)d_in[3];
    const float* proj_b = (const float*)d_in[4];
    float* out = (float*)d_out;

    // device-symbol addresses (host query, no allocation, capture-safe)
    float *q_p, *k_p, *v_p, *attn_p;
    cudaGetSymbolAddress((void**)&q_p,    g_q);
    cudaGetSymbolAddress((void**)&k_p,    g_k);
    cudaGetSymbolAddress((void**)&v_p,    g_v);
    cudaGetSymbolAddress((void**)&attn_p, g_attn);

    // 1. RoPE table
    rope_table_kernel<<<(N_ * 32 + 255) / 256, 256>>>();

    // 2. QKV GEMM + bias + RoPE scatter  (M=4096, NC=3072)
    {
        dim3 grid(4096 / 64, 3072 / 64);
        gemm64_kernel<true><<<grid, 256>>>(x, qkv_w, qkv_b, q_p, k_p, v_p);
    }

    // 3. causal flash attention -> g_attn [B,N,D]
    {
        dim3 grid(N_ / 64, B_ * H_);
        flash_kernel<<<grid, 256>>>(attn_p);
    }

    // 4. proj GEMM + bias -> d_out  (M=4096, NC=1024)
    {
        dim3 grid(4096 / 64, 1024 / 64);
        gemm64_kernel<false><<<grid, 256>>>(nullptr, proj_w, proj_b, out, nullptr, nullptr);
    }
}

// round 3
// speedup vs baseline: 1.1584x; 1.1584x over previous
#include <cuda_runtime.h>
#include <math.h>

#define B_  2
#define N_  2048
#define D_  1024
#define H_  16
#define HD_ 64

// Scratch (allocation-free rule: __device__ globals)
__device__ float g_q[B_*H_*N_*HD_];
__device__ float g_k[B_*H_*N_*HD_];
__device__ float g_v[B_*H_*N_*HD_];
__device__ float g_attn[B_*N_*D_];
__device__ float g_cos[N_*32];
__device__ float g_sin[N_*32];

// ---------------------------------------------------------------------------
// RoPE table
// ---------------------------------------------------------------------------
__global__ void rope_table_kernel() {
    int idx = blockIdx.x * blockDim.x + threadIdx.x;   // 65536
    if (idx >= N_ * 32) return;
    int n = idx >> 5;
    int p = idx & 31;
    float invf = (float)pow(10000.0, -(double)(2 * p) / (double)HD_);
    float ang_f = (float)n * invf;
    double ang = (double)ang_f;
    g_cos[idx] = (float)cos(ang);
    g_sin[idx] = (float)sin(ang);
}

// ---------------------------------------------------------------------------
// GEMM: C[M,NC] = A[M,1024] @ W[NC,1024]^T + bias
// 128x128 tile, BK=16, 256 threads, 8x8 microtile, double-buffered smem.
// ---------------------------------------------------------------------------
#define GEMM_COMPUTE(CUR)                                                   \
    {                                                                       \
        _Pragma("unroll")                                                   \
        for (int k = 0; k < 16; k++) {                                      \
            const float* as = &As[CUR][k][0];                               \
            const float* bs = &Bs[CUR][k][0];                               \
            float4 a0 = *(const float4*)(as + (ty << 2));                   \
            float4 a1 = *(const float4*)(as + 64 + (ty << 2));              \
            float4 b0 = *(const float4*)(bs + (tx << 2));                   \
            float4 b1 = *(const float4*)(bs + 64 + (tx << 2));              \
            float aa[8] = {a0.x,a0.y,a0.z,a0.w,a1.x,a1.y,a1.z,a1.w};        \
            float bb[8] = {b0.x,b0.y,b0.z,b0.w,b1.x,b1.y,b1.z,b1.w};        \
            _Pragma("unroll")                                               \
            for (int i = 0; i < 8; i++)                                     \
                _Pragma("unroll")                                           \
                for (int j = 0; j < 8; j++)                                 \
                    acc[i][j] += aa[i] * bb[j];                             \
        }                                                                   \
    }

#define GEMM_STORE(BUF)                                                     \
    {                                                                       \
        As[BUF][lk+0][lr]=pa0.x; As[BUF][lk+1][lr]=pa0.y;                   \
        As[BUF][lk+2][lr]=pa0.z; As[BUF][lk+3][lr]=pa0.w;                   \
        As[BUF][lk+4][lr]=pa1.x; As[BUF][lk+5][lr]=pa1.y;                   \
        As[BUF][lk+6][lr]=pa1.z; As[BUF][lk+7][lr]=pa1.w;                   \
        Bs[BUF][lk+0][lr]=pb0.x; Bs[BUF][lk+1][lr]=pb0.y;                   \
        Bs[BUF][lk+2][lr]=pb0.z; Bs[BUF][lk+3][lr]=pb0.w;                   \
        Bs[BUF][lk+4][lr]=pb1.x; Bs[BUF][lk+5][lr]=pb1.y;                   \
        Bs[BUF][lk+6][lr]=pb1.z; Bs[BUF][lk+7][lr]=pb1.w;                   \
    }

template<bool QKV>
__global__ void __launch_bounds__(256) gemm128_kernel(
    const float* __restrict__ A,
    const float* __restrict__ W,
    const float* __restrict__ bias,
    float* __restrict__ O0,
    float* __restrict__ O1,
    float* __restrict__ O2)
{
    __shared__ float As[2][16][128];
    __shared__ float Bs[2][16][128];
    const int K = 1024;

    int tid = threadIdx.x;
    int tx = tid & 15, ty = tid >> 4;
    int m0 = blockIdx.x * 128, n0 = blockIdx.y * 128;
    int lr = tid >> 1;
    int lk = (tid & 1) << 3;

    const float* Abase = QKV ? A : (const float*)g_attn;
    const float* Ap = Abase + (size_t)(m0 + lr) * K + lk;
    const float* Wp = W     + (size_t)(n0 + lr) * K + lk;

    float acc[8][8] = {};

    float4 pa0 = *(const float4*)(Ap);
    float4 pa1 = *(const float4*)(Ap + 4);
    float4 pb0 = *(const float4*)(Wp);
    float4 pb1 = *(const float4*)(Wp + 4);

    int cur = 0;
    GEMM_STORE(0);
    __syncthreads();

#pragma unroll 1
    for (int it = 0; it < 63; it++) {
        int k0 = (it + 1) << 4;
        pa0 = *(const float4*)(Ap + k0);
        pa1 = *(const float4*)(Ap + k0 + 4);
        pb0 = *(const float4*)(Wp + k0);
        pb1 = *(const float4*)(Wp + k0 + 4);
        GEMM_COMPUTE(cur);
        GEMM_STORE(cur ^ 1);
        __syncthreads();
        cur ^= 1;
    }
    GEMM_COMPUTE(cur);

    // --- epilogue ---
    float bi0[4], bi1[4];
#pragma unroll
    for (int j = 0; j < 4; j++) {
        bi0[j] = bias[n0 + (tx << 2) + j];
        bi1[j] = bias[n0 + 64 + (tx << 2) + j];
    }

    if (!QKV) {
#pragma unroll
        for (int rg = 0; rg < 2; rg++)
#pragma unroll
        for (int i = 0; i < 4; i++) {
            int m = m0 + rg * 64 + (ty << 2) + i;
            float* r = O0 + (size_t)m * 1024 + n0 + (tx << 2);
            *(float4*)r = make_float4(acc[rg*4+i][0]+bi0[0], acc[rg*4+i][1]+bi0[1],
                                      acc[rg*4+i][2]+bi0[2], acc[rg*4+i][3]+bi0[3]);
            *(float4*)(r + 64) = make_float4(acc[rg*4+i][4]+bi1[0], acc[rg*4+i][5]+bi1[1],
                                             acc[rg*4+i][6]+bi1[2], acc[rg*4+i][7]+bi1[3]);
        }
    } else {
        int region = n0 >> 10;                  // 0=q 1=k 2=v
        int h0 = (n0 & 1023) >> 6;              // head of col-group 0; group1 = h0+1
        float* dst = (region == 0) ? O0 : (region == 1) ? O1 : O2;
        int p0 = tx << 1;                        // rope pair indices (same for both groups)
#pragma unroll
        for (int rg = 0; rg < 2; rg++)
#pragma unroll
        for (int i = 0; i < 4; i++) {
            int m = m0 + rg * 64 + (ty << 2) + i;
            int b_ = m >> 11;
            int n  = m & 2047;
            float c0 = 1.f, s0 = 0.f, c1 = 1.f, s1 = 0.f;
            if (region < 2) {
                c0 = g_cos[n*32 + p0];     s0 = g_sin[n*32 + p0];
                c1 = g_cos[n*32 + p0 + 1]; s1 = g_sin[n*32 + p0 + 1];
            }
#pragma unroll
            for (int g = 0; g < 2; g++) {
                float v0 = acc[rg*4+i][g*4+0] + (g ? bi1[0] : bi0[0]);
                float v1 = acc[rg*4+i][g*4+1] + (g ? bi1[1] : bi0[1]);
                float v2 = acc[rg*4+i][g*4+2] + (g ? bi1[2] : bi0[2]);
                float v3 = acc[rg*4+i][g*4+3] + (g ? bi1[3] : bi0[3]);
                if (region < 2) {
                    float r0 = v0*c0 - v1*s0, r1 = v1*c0 + v0*s0;
                    float r2 = v2*c1 - v3*s1, r3 = v3*c1 + v2*s1;
                    v0 = r0; v1 = r1; v2 = r2; v3 = r3;
                }
                int h = h0 + g;
                *(float4*)(dst + ((size_t)(b_*H_ + h) * N_ + n) * HD_ + (tx << 2)) =
                    make_float4(v0, v1, v2, v3);
            }
        }
    }
}

// ---------------------------------------------------------------------------
// Flash attention: BM=128, BN=64. 256 threads, 8x4 microtile.
// Qt [64][128] transposed+swizzled, Kt [64][64] transposed+swizzled,
// Ps [128][68], Vs [64][64]. Dynamic smem 100352 B.
// ---------------------------------------------------------------------------
#define QT_OFF(d, c)  ((d)*128 + ((((c) ^ ((d) & 15))) << 2))   // c = chunk 0..31
#define KT_OFF(d, c)  ((d)*64  + ((((c) ^ ((d) & 15))) << 2))   // c = chunk 0..15
#define PS_STRIDE 68

__global__ void __launch_bounds__(256) flash_kernel(float* __restrict__ Og) {
    extern __shared__ float sm[];
    float* Qt = sm;                       // 64*128  = 8192
    float* Kt = Qt + 64*128;              // 64*64   = 4096
    float* Ps = Kt + 64*64;               // 128*68  = 8704
    float* Vs = Ps + 128*PS_STRIDE;       // 64*64   = 4096

    int tid = threadIdx.x;
    int tx = tid & 15, ty = tid >> 4;
    int mt = blockIdx.x;
    int bh = blockIdx.y;
    int m0 = mt * 128;

    const float* Qb = g_q + (size_t)bh * N_ * HD_;
    const float* Kb = g_k + (size_t)bh * N_ * HD_;
    const float* Vb = g_v + (size_t)bh * N_ * HD_;

    int r0 = (tid & 15) << 2;     // transpose-block row base
    int d0 = (tid >> 4) << 2;     // transpose-block dim base

    // Q load + 4x4 register transpose + swizzled store (scaled)
    {
        const float sc = 0.125f;
#pragma unroll
        for (int pass = 0; pass < 2; pass++) {
            int r = r0 + pass * 64;
            float4 v[4];
#pragma unroll
            for (int i = 0; i < 4; i++)
                v[i] = *(const float4*)(Qb + (size_t)(m0 + r + i) * HD_ + d0);
            const float* vp = (const float*)v;
#pragma unroll
            for (int j = 0; j < 4; j++) {
                float4 w = make_float4(vp[0*4+j]*sc, vp[1*4+j]*sc, vp[2*4+j]*sc, vp[3*4+j]*sc);
                *(float4*)&Qt[QT_OFF(d0 + j, (r >> 2))] = w;
            }
        }
    }

    float o[8][4] = {};
    float mrow[8], lrow[8];
#pragma unroll
    for (int i = 0; i < 8; i++) { mrow[i] = -1e30f; lrow[i] = 0.f; }

    int row_of[8];
#pragma unroll
    for (int i = 0; i < 8; i++)
        row_of[i] = (i >> 2) * 64 + (ty << 2) + (i & 3);   // row within tile

    int ntmax = 2 * mt + 1;
    for (int nt = 0; nt <= ntmax; nt++) {
        int n0k = nt * 64;
        __syncthreads();   // Qt ready / prev iter done with Kt, Ps, Vs

        // K: load + transpose + swizzled store
        {
            float4 v[4];
#pragma unroll
            for (int i = 0; i < 4; i++)
                v[i] = *(const float4*)(Kb + (size_t)(n0k + r0 + i) * HD_ + d0);
            const float* vp = (const float*)v;
#pragma unroll
            for (int j = 0; j < 4; j++)
                *(float4*)&Kt[KT_OFF(d0 + j, (r0 >> 2))] =
                    make_float4(vp[0*4+j], vp[1*4+j], vp[2*4+j], vp[3*4+j]);
        }
        // V: straight copy, coalesced
#pragma unroll
        for (int t = 0; t < 4; t++) {
            int idx = tid + t * 256;
            int r = idx >> 4, d = (idx & 15) << 2;
            *(float4*)&Vs[r * 64 + d] = *(const float4*)(Vb + (size_t)(n0k + r) * HD_ + d);
        }
        __syncthreads();

        // S = Qs @ K^T  (Q pre-scaled)
        float s[8][4] = {};
#pragma unroll 8
        for (int d = 0; d < 64; d++) {
            float4 a0 = *(const float4*)&Qt[QT_OFF(d, ty)];
            float4 a1 = *(const float4*)&Qt[QT_OFF(d, 16 + ty)];
            float4 b  = *(const float4*)&Kt[KT_OFF(d, tx)];
            float aa[8] = {a0.x,a0.y,a0.z,a0.w,a1.x,a1.y,a1.z,a1.w};
            float bb[4] = {b.x,b.y,b.z,b.w};
#pragma unroll
            for (int i = 0; i < 8; i++)
#pragma unroll
                for (int j = 0; j < 4; j++)
                    s[i][j] += aa[i] * bb[j];
        }

        if (nt >= 2 * mt) {   // masking only needed near diagonal
#pragma unroll
            for (int i = 0; i < 8; i++)
#pragma unroll
                for (int j = 0; j < 4; j++)
                    if (n0k + (tx << 2) + j > m0 + row_of[i]) s[i][j] = -1e30f;
        }

        // online softmax (16-lane row groups)
#pragma unroll
        for (int i = 0; i < 8; i++) {
            float mx = fmaxf(fmaxf(s[i][0], s[i][1]), fmaxf(s[i][2], s[i][3]));
#pragma unroll
            for (int off = 1; off < 16; off <<= 1)
                mx = fmaxf(mx, __shfl_xor_sync(0xffffffffu, mx, off));
            float mn = fmaxf(mrow[i], mx);
            float al = __expf(mrow[i] - mn);
            mrow[i] = mn;
            float rs = 0.f;
#pragma unroll
            for (int j = 0; j < 4; j++) {
                float p = __expf(s[i][j] - mn);
                s[i][j] = p;
                rs += p;
            }
#pragma unroll
            for (int off = 1; off < 16; off <<= 1)
                rs += __shfl_xor_sync(0xffffffffu, rs, off);
            lrow[i] = lrow[i] * al + rs;
#pragma unroll
            for (int j = 0; j < 4; j++) o[i][j] *= al;
        }

        // store P
#pragma unroll
        for (int i = 0; i < 8; i++)
            *(float4*)&Ps[row_of[i] * PS_STRIDE + (tx << 2)] =
                make_float4(s[i][0], s[i][1], s[i][2], s[i][3]);
        __syncthreads();

        // O += P @ V
#pragma unroll 8
        for (int c = 0; c < 64; c++) {
            float4 b = *(const float4*)&Vs[c * 64 + (tx << 2)];
            float bb[4] = {b.x, b.y, b.z, b.w};
#pragma unroll
            for (int i = 0; i < 8; i++) {
                float a = Ps[row_of[i] * PS_STRIDE + c];
#pragma unroll
                for (int j = 0; j < 4; j++)
                    o[i][j] += a * bb[j];
            }
        }
    }

    // epilogue
    int b_ = bh >> 4, h = bh & 15;
#pragma unroll
    for (int i = 0; i < 8; i++) {
        int m = m0 + row_of[i];
        float inv = 1.f / lrow[i];
        *(float4*)(Og + ((size_t)(b_ * N_ + m) * D_) + h * HD_ + (tx << 2)) =
            make_float4(o[i][0]*inv, o[i][1]*inv, o[i][2]*inv, o[i][3]*inv);
    }
}

// ---------------------------------------------------------------------------
extern "C" void kernel_launch(void* const* d_in, const int* in_sizes, int n_in,
                              void* d_out, int out_size)
{
    const float* x      = (const float*)d_in[0];
    const float* qkv_w  = (const float*)d_in[1];
    const float* qkv_b  = (const float*)d_in[2];
    const float* proj_w = (const float*)d_in[3];
    const float* proj_b = (const float*)d_in[4];
    float* out = (float*)d_out;

    float *q_p, *k_p, *v_p, *attn_p;
    cudaGetSymbolAddress((void**)&q_p,    g_q);
    cudaGetSymbolAddress((void**)&k_p,    g_k);
    cudaGetSymbolAddress((void**)&v_p,    g_v);
    cudaGetSymbolAddress((void**)&attn_p, g_attn);

    const int FLASH_SMEM = (64*128 + 64*64 + 128*PS_STRIDE + 64*64) * 4;
    cudaFuncSetAttribute(flash_kernel, cudaFuncAttributeMaxDynamicSharedMemorySize, FLASH_SMEM);

    rope_table_kernel<<<(N_ * 32 + 255) / 256, 256>>>();

    {   // QKV GEMM: M=4096, NC=3072
        dim3 grid(4096 / 128, 3072 / 128);
        gemm128_kernel<true><<<grid, 256>>>(x, qkv_w, qkv_b, q_p, k_p, v_p);
    }
    {   // flash attention
        dim3 grid(N_ / 128, B_ * H_);
        flash_kernel<<<grid, 256, FLASH_SMEM>>>(attn_p);
    }
    {   // proj GEMM: M=4096, NC=1024
        dim3 grid(4096 / 128, 1024 / 128);
        gemm128_kernel<false><<<grid, 256>>>(nullptr, proj_w, proj_b, out, nullptr, nullptr);
    }
}

// round 4
// speedup vs baseline: 1.1735x; 1.0130x over previous
#include <cuda_runtime.h>
#include <math.h>

#define B_  2
#define N_  2048
#define D_  1024
#define H_  16
#define HD_ 64

// Scratch (allocation-free rule: __device__ globals)
__device__ float g_q[B_*H_*N_*HD_];
__device__ float g_k[B_*H_*N_*HD_];
__device__ float g_v[B_*H_*N_*HD_];
__device__ float g_attn[B_*N_*D_];
__device__ float g_cos[N_*32];
__device__ float g_sin[N_*32];

// ---------------------------------------------------------------------------
// RoPE table
// ---------------------------------------------------------------------------
__global__ void rope_table_kernel() {
    int idx = blockIdx.x * blockDim.x + threadIdx.x;   // 65536
    if (idx >= N_ * 32) return;
    int n = idx >> 5;
    int p = idx & 31;
    float invf = (float)pow(10000.0, -(double)(2 * p) / (double)HD_);
    float ang_f = (float)n * invf;
    double ang = (double)ang_f;
    g_cos[idx] = (float)cos(ang);
    g_sin[idx] = (float)sin(ang);
}

// ---------------------------------------------------------------------------
// GEMM: C[M,NC] = A[M,1024] @ W[NC,1024]^T + bias
// 128x128 tile, BK=16, 256 threads, 8x8 microtile, double-buffered smem.
// __launch_bounds__(256,2): cap at 128 regs so 2 CTAs/SM co-reside.
// ---------------------------------------------------------------------------
#define GEMM_COMPUTE(CUR)                                                   \
    {                                                                       \
        _Pragma("unroll")                                                   \
        for (int k = 0; k < 16; k++) {                                      \
            const float* as = &As[CUR][k][0];                               \
            const float* bs = &Bs[CUR][k][0];                               \
            float4 a0 = *(const float4*)(as + (ty << 2));                   \
            float4 a1 = *(const float4*)(as + 64 + (ty << 2));              \
            float4 b0 = *(const float4*)(bs + (tx << 2));                   \
            float4 b1 = *(const float4*)(bs + 64 + (tx << 2));              \
            float aa[8] = {a0.x,a0.y,a0.z,a0.w,a1.x,a1.y,a1.z,a1.w};        \
            float bb[8] = {b0.x,b0.y,b0.z,b0.w,b1.x,b1.y,b1.z,b1.w};        \
            _Pragma("unroll")                                               \
            for (int i = 0; i < 8; i++)                                     \
                _Pragma("unroll")                                           \
                for (int j = 0; j < 8; j++)                                 \
                    acc[i][j] += aa[i] * bb[j];                             \
        }                                                                   \
    }

#define GEMM_STORE(BUF)                                                     \
    {                                                                       \
        As[BUF][lk+0][lr]=pa0.x; As[BUF][lk+1][lr]=pa0.y;                   \
        As[BUF][lk+2][lr]=pa0.z; As[BUF][lk+3][lr]=pa0.w;                   \
        As[BUF][lk+4][lr]=pa1.x; As[BUF][lk+5][lr]=pa1.y;                   \
        As[BUF][lk+6][lr]=pa1.z; As[BUF][lk+7][lr]=pa1.w;                   \
        Bs[BUF][lk+0][lr]=pb0.x; Bs[BUF][lk+1][lr]=pb0.y;                   \
        Bs[BUF][lk+2][lr]=pb0.z; Bs[BUF][lk+3][lr]=pb0.w;                   \
        Bs[BUF][lk+4][lr]=pb1.x; Bs[BUF][lk+5][lr]=pb1.y;                   \
        Bs[BUF][lk+6][lr]=pb1.z; Bs[BUF][lk+7][lr]=pb1.w;                   \
    }

template<bool QKV>
__global__ void __launch_bounds__(256, 2) gemm128_kernel(
    const float* __restrict__ A,
    const float* __restrict__ W,
    const float* __restrict__ bias,
    float* __restrict__ O0,
    float* __restrict__ O1,
    float* __restrict__ O2)
{
    __shared__ float As[2][16][128];
    __shared__ float Bs[2][16][128];
    const int K = 1024;

    int tid = threadIdx.x;
    int tx = tid & 15, ty = tid >> 4;
    int m0 = blockIdx.y * 128, n0 = blockIdx.x * 128;   // x = N dim (W reuse across x)
    int lr = tid >> 1;
    int lk = (tid & 1) << 3;

    const float* Abase = QKV ? A : (const float*)g_attn;
    const float* Ap = Abase + (size_t)(m0 + lr) * K + lk;
    const float* Wp = W     + (size_t)(n0 + lr) * K + lk;

    float acc[8][8] = {};

    float4 pa0 = *(const float4*)(Ap);
    float4 pa1 = *(const float4*)(Ap + 4);
    float4 pb0 = *(const float4*)(Wp);
    float4 pb1 = *(const float4*)(Wp + 4);

    int cur = 0;
    GEMM_STORE(0);
    __syncthreads();

#pragma unroll 1
    for (int it = 0; it < 63; it++) {
        int k0 = (it + 1) << 4;
        pa0 = *(const float4*)(Ap + k0);
        pa1 = *(const float4*)(Ap + k0 + 4);
        pb0 = *(const float4*)(Wp + k0);
        pb1 = *(const float4*)(Wp + k0 + 4);
        GEMM_COMPUTE(cur);
        GEMM_STORE(cur ^ 1);
        __syncthreads();
        cur ^= 1;
    }
    GEMM_COMPUTE(cur);

    // --- epilogue ---
    float bi0[4], bi1[4];
#pragma unroll
    for (int j = 0; j < 4; j++) {
        bi0[j] = bias[n0 + (tx << 2) + j];
        bi1[j] = bias[n0 + 64 + (tx << 2) + j];
    }

    if (!QKV) {
#pragma unroll
        for (int rg = 0; rg < 2; rg++)
#pragma unroll
        for (int i = 0; i < 4; i++) {
            int m = m0 + rg * 64 + (ty << 2) + i;
            float* r = O0 + (size_t)m * 1024 + n0 + (tx << 2);
            *(float4*)r = make_float4(acc[rg*4+i][0]+bi0[0], acc[rg*4+i][1]+bi0[1],
                                      acc[rg*4+i][2]+bi0[2], acc[rg*4+i][3]+bi0[3]);
            *(float4*)(r + 64) = make_float4(acc[rg*4+i][4]+bi1[0], acc[rg*4+i][5]+bi1[1],
                                             acc[rg*4+i][6]+bi1[2], acc[rg*4+i][7]+bi1[3]);
        }
    } else {
        int region = n0 >> 10;                  // 0=q 1=k 2=v
        int h0 = (n0 & 1023) >> 6;              // head of col-group 0; group1 = h0+1
        float* dst = (region == 0) ? O0 : (region == 1) ? O1 : O2;
        int p0 = tx << 1;                        // rope pair indices
#pragma unroll
        for (int rg = 0; rg < 2; rg++)
#pragma unroll
        for (int i = 0; i < 4; i++) {
            int m = m0 + rg * 64 + (ty << 2) + i;
            int b_ = m >> 11;
            int n  = m & 2047;
            float c0 = 1.f, s0 = 0.f, c1 = 1.f, s1 = 0.f;
            if (region < 2) {
                c0 = g_cos[n*32 + p0];     s0 = g_sin[n*32 + p0];
                c1 = g_cos[n*32 + p0 + 1]; s1 = g_sin[n*32 + p0 + 1];
            }
#pragma unroll
            for (int g = 0; g < 2; g++) {
                float v0 = acc[rg*4+i][g*4+0] + (g ? bi1[0] : bi0[0]);
                float v1 = acc[rg*4+i][g*4+1] + (g ? bi1[1] : bi0[1]);
                float v2 = acc[rg*4+i][g*4+2] + (g ? bi1[2] : bi0[2]);
                float v3 = acc[rg*4+i][g*4+3] + (g ? bi1[3] : bi0[3]);
                if (region < 2) {
                    float r0 = v0*c0 - v1*s0, r1 = v1*c0 + v0*s0;
                    float r2 = v2*c1 - v3*s1, r3 = v3*c1 + v2*s1;
                    v0 = r0; v1 = r1; v2 = r2; v3 = r3;
                }
                int h = h0 + g;
                *(float4*)(dst + ((size_t)(b_*H_ + h) * N_ + n) * HD_ + (tx << 2)) =
                    make_float4(v0, v1, v2, v3);
            }
        }
    }
}

// ---------------------------------------------------------------------------
// Flash attention: BM=128, BN=64. 256 threads, 8x4 microtile.
// Qt [64][128] transposed+swizzled, Kt [64][64] transposed+swizzled,
// Ps [128][68], Vs [64][64]. Dynamic smem 100352 B -> 2 CTAs/SM.
// ---------------------------------------------------------------------------
#define QT_OFF(d, c)  ((d)*128 + ((((c) ^ ((d) & 15))) << 2))   // c = chunk 0..31
#define KT_OFF(d, c)  ((d)*64  + ((((c) ^ ((d) & 15))) << 2))   // c = chunk 0..15
#define PS_STRIDE 68

__global__ void __launch_bounds__(256, 2) flash_kernel(float* __restrict__ Og) {
    extern __shared__ float sm[];
    float* Qt = sm;                       // 64*128  = 8192
    float* Kt = Qt + 64*128;              // 64*64   = 4096
    float* Ps = Kt + 64*64;               // 128*68  = 8704
    float* Vs = Ps + 128*PS_STRIDE;       // 64*64   = 4096

    int tid = threadIdx.x;
    int tx = tid & 15, ty = tid >> 4;
    int mt = blockIdx.x;
    int bh = blockIdx.y;
    int m0 = mt * 128;

    const float* Qb = g_q + (size_t)bh * N_ * HD_;
    const float* Kb = g_k + (size_t)bh * N_ * HD_;
    const float* Vb = g_v + (size_t)bh * N_ * HD_;

    int r0 = (tid & 15) << 2;     // transpose-block row base
    int d0 = (tid >> 4) << 2;     // transpose-block dim base

    // Q load + 4x4 register transpose + swizzled store (scaled)
    {
        const float sc = 0.125f;
#pragma unroll
        for (int pass = 0; pass < 2; pass++) {
            int r = r0 + pass * 64;
            float4 v[4];
#pragma unroll
            for (int i = 0; i < 4; i++)
                v[i] = *(const float4*)(Qb + (size_t)(m0 + r + i) * HD_ + d0);
            const float* vp = (const float*)v;
#pragma unroll
            for (int j = 0; j < 4; j++) {
                float4 w = make_float4(vp[0*4+j]*sc, vp[1*4+j]*sc, vp[2*4+j]*sc, vp[3*4+j]*sc);
                *(float4*)&Qt[QT_OFF(d0 + j, (r >> 2))] = w;
            }
        }
    }

    float o[8][4] = {};
    float mrow[8], lrow[8];
#pragma unroll
    for (int i = 0; i < 8; i++) { mrow[i] = -1e30f; lrow[i] = 0.f; }

    int row_of[8];
#pragma unroll
    for (int i = 0; i < 8; i++)
        row_of[i] = (i >> 2) * 64 + (ty << 2) + (i & 3);   // row within tile

    int ntmax = 2 * mt + 1;
    for (int nt = 0; nt <= ntmax; nt++) {
        int n0k = nt * 64;
        __syncthreads();   // Qt ready / prev iter done with Kt, Ps, Vs

        // K: load + transpose + swizzled store
        {
            float4 v[4];
#pragma unroll
            for (int i = 0; i < 4; i++)
                v[i] = *(const float4*)(Kb + (size_t)(n0k + r0 + i) * HD_ + d0);
            const float* vp = (const float*)v;
#pragma unroll
            for (int j = 0; j < 4; j++)
                *(float4*)&Kt[KT_OFF(d0 + j, (r0 >> 2))] =
                    make_float4(vp[0*4+j], vp[1*4+j], vp[2*4+j], vp[3*4+j]);
        }
        // V: straight copy, coalesced
#pragma unroll
        for (int t = 0; t < 4; t++) {
            int idx = tid + t * 256;
            int r = idx >> 4, d = (idx & 15) << 2;
            *(float4*)&Vs[r * 64 + d] = *(const float4*)(Vb + (size_t)(n0k + r) * HD_ + d);
        }
        __syncthreads();

        // S = Qs @ K^T  (Q pre-scaled)
        float s[8][4] = {};
#pragma unroll 8
        for (int d = 0; d < 64; d++) {
            float4 a0 = *(const float4*)&Qt[QT_OFF(d, ty)];
            float4 a1 = *(const float4*)&Qt[QT_OFF(d, 16 + ty)];
            float4 b  = *(const float4*)&Kt[KT_OFF(d, tx)];
            float aa[8] = {a0.x,a0.y,a0.z,a0.w,a1.x,a1.y,a1.z,a1.w};
            float bb[4] = {b.x,b.y,b.z,b.w};
#pragma unroll
            for (int i = 0; i < 8; i++)
#pragma unroll
                for (int j = 0; j < 4; j++)
                    s[i][j] += aa[i] * bb[j];
        }

        if (nt >= 2 * mt) {   // masking only needed near diagonal
#pragma unroll
            for (int i = 0; i < 8; i++)
#pragma unroll
                for (int j = 0; j < 4; j++)
                    if (n0k + (tx << 2) + j > m0 + row_of[i]) s[i][j] = -1e30f;
        }

        // online softmax (16-lane row groups)
#pragma unroll
        for (int i = 0; i < 8; i++) {
            float mx = fmaxf(fmaxf(s[i][0], s[i][1]), fmaxf(s[i][2], s[i][3]));
#pragma unroll
            for (int off = 1; off < 16; off <<= 1)
                mx = fmaxf(mx, __shfl_xor_sync(0xffffffffu, mx, off));
            float mn = fmaxf(mrow[i], mx);
            float al = __expf(mrow[i] - mn);
            mrow[i] = mn;
            float rs = 0.f;
#pragma unroll
            for (int j = 0; j < 4; j++) {
                float p = __expf(s[i][j] - mn);
                s[i][j] = p;
                rs += p;
            }
#pragma unroll
            for (int off = 1; off < 16; off <<= 1)
                rs += __shfl_xor_sync(0xffffffffu, rs, off);
            lrow[i] = lrow[i] * al + rs;
#pragma unroll
            for (int j = 0; j < 4; j++) o[i][j] *= al;
        }

        // store P
#pragma unroll
        for (int i = 0; i < 8; i++)
            *(float4*)&Ps[row_of[i] * PS_STRIDE + (tx << 2)] =
                make_float4(s[i][0], s[i][1], s[i][2], s[i][3]);
        __syncthreads();

        // O += P @ V
#pragma unroll 8
        for (int c = 0; c < 64; c++) {
            float4 b = *(const float4*)&Vs[c * 64 + (tx << 2)];
            float bb[4] = {b.x, b.y, b.z, b.w};
#pragma unroll
            for (int i = 0; i < 8; i++) {
                float a = Ps[row_of[i] * PS_STRIDE + c];
#pragma unroll
                for (int j = 0; j < 4; j++)
                    o[i][j] += a * bb[j];
            }
        }
    }

    // epilogue
    int b_ = bh >> 4, h = bh & 15;
#pragma unroll
    for (int i = 0; i < 8; i++) {
        int m = m0 + row_of[i];
        float inv = 1.f / lrow[i];
        *(float4*)(Og + ((size_t)(b_ * N_ + m) * D_) + h * HD_ + (tx << 2)) =
            make_float4(o[i][0]*inv, o[i][1]*inv, o[i][2]*inv, o[i][3]*inv);
    }
}

// ---------------------------------------------------------------------------
extern "C" void kernel_launch(void* const* d_in, const int* in_sizes, int n_in,
                              void* d_out, int out_size)
{
    const float* x      = (const float*)d_in[0];
    const float* qkv_w  = (const float*)d_in[1];
    const float* qkv_b  = (const float*)d_in[2];
    const float* proj_w = (const float*)d_in[3];
    const float* proj_b = (const float*)d_in[4];
    float* out = (float*)d_out;

    float *q_p, *k_p, *v_p, *attn_p;
    cudaGetSymbolAddress((void**)&q_p,    g_q);
    cudaGetSymbolAddress((void**)&k_p,    g_k);
    cudaGetSymbolAddress((void**)&v_p,    g_v);
    cudaGetSymbolAddress((void**)&attn_p, g_attn);

    const int FLASH_SMEM = (64*128 + 64*64 + 128*PS_STRIDE + 64*64) * 4;
    cudaFuncSetAttribute(flash_kernel, cudaFuncAttributeMaxDynamicSharedMemorySize, FLASH_SMEM);

    rope_table_kernel<<<(N_ * 32 + 255) / 256, 256>>>();

    {   // QKV GEMM: M=4096, NC=3072
        dim3 grid(3072 / 128, 4096 / 128);
        gemm128_kernel<true><<<grid, 256>>>(x, qkv_w, qkv_b, q_p, k_p, v_p);
    }
    {   // flash attention
        dim3 grid(N_ / 128, B_ * H_);
        flash_kernel<<<grid, 256, FLASH_SMEM>>>(attn_p);
    }
    {   // proj GEMM: M=4096, NC=1024
        dim3 grid(1024 / 128, 4096 / 128);
        gemm128_kernel<false><<<grid, 256>>>(nullptr, proj_w, proj_b, out, nullptr, nullptr);
    }
}

// round 8
// speedup vs baseline: 1.4016x; 1.1944x over previous
#include <cuda_runtime.h>
#include <cuda_bf16.h>
#include <math.h>
#include <stdint.h>

#define B_  2
#define N_  2048
#define D_  1024
#define H_  16
#define HD_ 64

// fp32 scratch
__device__ float g_q[B_*H_*N_*HD_];
__device__ float g_k[B_*H_*N_*HD_];
__device__ float g_v[B_*H_*N_*HD_];
__device__ float g_attn[B_*N_*D_];
__device__ float g_cos[N_*32];
__device__ float g_sin[N_*32];

// bf16 hi/lo operand arrays
__device__ __nv_bfloat16 g_xhi[4096*1024], g_xlo[4096*1024];
__device__ __nv_bfloat16 g_wqh[3072*1024], g_wql[3072*1024];
__device__ __nv_bfloat16 g_wph[1024*1024], g_wpl[1024*1024];
__device__ __nv_bfloat16 g_ahi[4096*1024], g_alo[4096*1024];

// ---------------------------------------------------------------------------
// Target-agnostic tensor-core helpers (sm_80+ PTX; no 'a'-suffix features)
// ---------------------------------------------------------------------------
__device__ __forceinline__ uint32_t smem_u32(const void* p) {
    uint32_t a;
    asm("{ .reg .u64 t; cvta.to.shared.u64 t, %1; cvt.u32.u64 %0, t; }" : "=r"(a) : "l"(p));
    return a;
}
__device__ __forceinline__ void ldsm_x4(uint32_t* r, uint32_t addr) {
    asm volatile("ldmatrix.sync.aligned.m8n8.x4.shared.b16 {%0,%1,%2,%3}, [%4];"
        : "=r"(r[0]), "=r"(r[1]), "=r"(r[2]), "=r"(r[3]) : "r"(addr));
}
__device__ __forceinline__ void ldsm_x2(uint32_t* r, uint32_t addr) {
    asm volatile("ldmatrix.sync.aligned.m8n8.x2.shared.b16 {%0,%1}, [%2];"
        : "=r"(r[0]), "=r"(r[1]) : "r"(addr));
}
__device__ __forceinline__ void mma16816(float* c,
    uint32_t a0, uint32_t a1, uint32_t a2, uint32_t a3, uint32_t b0, uint32_t b1) {
    asm volatile(
        "mma.sync.aligned.m16n8k16.row.col.f32.bf16.bf16.f32 "
        "{%0,%1,%2,%3}, {%4,%5,%6,%7}, {%8,%9}, {%0,%1,%2,%3};"
        : "+f"(c[0]), "+f"(c[1]), "+f"(c[2]), "+f"(c[3])
        : "r"(a0), "r"(a1), "r"(a2), "r"(a3), "r"(b0), "r"(b1));
}

// ---------------------------------------------------------------------------
// RoPE table
// ---------------------------------------------------------------------------
__global__ void rope_table_kernel() {
    int idx = blockIdx.x * blockDim.x + threadIdx.x;
    if (idx >= N_ * 32) return;
    int n = idx >> 5;
    int p = idx & 31;
    float invf = (float)pow(10000.0, -(double)(2 * p) / (double)HD_);
    float ang_f = (float)n * invf;
    double ang = (double)ang_f;
    g_cos[idx] = (float)cos(ang);
    g_sin[idx] = (float)sin(ang);
}

// ---------------------------------------------------------------------------
// fp32 -> bf16 hi/lo split converter
// ---------------------------------------------------------------------------
__global__ void cvt_hilo_kernel(const float4* __restrict__ src,
                                uint2* __restrict__ hi, uint2* __restrict__ lo, int n4) {
    int i = blockIdx.x * blockDim.x + threadIdx.x;
    if (i >= n4) return;
    float4 v = src[i];
    __nv_bfloat162 h01 = __floats2bfloat162_rn(v.x, v.y);
    __nv_bfloat162 h23 = __floats2bfloat162_rn(v.z, v.w);
    float r0 = v.x - __low2float(h01), r1 = v.y - __high2float(h01);
    float r2 = v.z - __low2float(h23), r3 = v.w - __high2float(h23);
    __nv_bfloat162 l01 = __floats2bfloat162_rn(r0, r1);
    __nv_bfloat162 l23 = __floats2bfloat162_rn(r2, r3);
    uint2 hw, lw;
    hw.x = *reinterpret_cast<const unsigned*>(&h01);
    hw.y = *reinterpret_cast<const unsigned*>(&h23);
    lw.x = *reinterpret_cast<const unsigned*>(&l01);
    lw.y = *reinterpret_cast<const unsigned*>(&l23);
    hi[i] = hw;
    lo[i] = lw;
}

// ---------------------------------------------------------------------------
// Tensor-core GEMM via mma.sync: C[M,NC] = A[M,1024] @ W[NC,1024]^T + bias.
// 3-term bf16 hi/lo split as 3 linearized K-passes (AhWh, AhWl, AlWh).
// CTA 128x128, 8 warps (2m x 4n), warp tile 64x32, BK=32, double-buffered.
// smem rows: 32 bf16 = 64B data, stride 80B (conflict-free ldmatrix).
// qkv=1: fused bias + RoPE + q/k/v scatter. qkv=0: bias + store to O0.
// ---------------------------------------------------------------------------
__global__ void __launch_bounds__(256, 2)
mma_gemm_kernel(const __nv_bfloat16* __restrict__ Ah, const __nv_bfloat16* __restrict__ Al,
                const __nv_bfloat16* __restrict__ Wh, const __nv_bfloat16* __restrict__ Wl,
                const float* __restrict__ bias,
                float* __restrict__ O0, float* __restrict__ O1, float* __restrict__ O2,
                int qkv)
{
    __shared__ __align__(16) char sm[40960];   // A[2]:0,10240 ; W[2]:20480,30720
    uint32_t sb = smem_u32(sm);

    int tid = threadIdx.x;
    int lane = tid & 31;
    int wid = tid >> 5;
    int warp_m = wid & 1;          // 0..1  -> 64 rows each
    int warp_n = wid >> 1;         // 0..3  -> 32 cols each
    int n0 = blockIdx.x * 128, m0 = blockIdx.y * 128;

    const __nv_bfloat16* Asel[3] = {Ah, Ah, Al};
    const __nv_bfloat16* Wsel[3] = {Wh, Wl, Wh};

    // global-load assignment: row lr (0..127), 16 bf16 starting at col lc (0/16)
    int lr = tid >> 1;
    int lc = (tid & 1) << 4;

    // ldmatrix base offsets (within a buffer)
    uint32_t a_off = (uint32_t)((warp_m * 64 + (lane & 15)) * 80 + ((lane >> 4) << 4));
    uint32_t b_off = (uint32_t)((warp_n * 32 + (lane & 7)) * 80 + (((lane >> 3) & 1) << 4));

    float acc[4][4][4];
#pragma unroll
    for (int i = 0; i < 4; i++)
#pragma unroll
        for (int j = 0; j < 4; j++)
#pragma unroll
            for (int q = 0; q < 4; q++) acc[i][j][q] = 0.f;

    uint4 va0, va1, vw0, vw1;
    {   // prefetch chunk 0 (pass 0)
        const __nv_bfloat16* ap = Asel[0] + (size_t)(m0 + lr) * 1024 + lc;
        const __nv_bfloat16* wp = Wsel[0] + (size_t)(n0 + lr) * 1024 + lc;
        va0 = *(const uint4*)ap; va1 = *(const uint4*)(ap + 8);
        vw0 = *(const uint4*)wp; vw1 = *(const uint4*)(wp + 8);
    }
    {   // store chunk 0 -> buf 0
        uint32_t so = (uint32_t)(lr * 80 + lc * 2);
        *(uint4*)(sm + so)          = va0;
        *(uint4*)(sm + so + 16)     = va1;
        *(uint4*)(sm + 20480 + so)      = vw0;
        *(uint4*)(sm + 20480 + so + 16) = vw1;
    }
    __syncthreads();

    int buf = 0;
#pragma unroll 1
    for (int ck = 0; ck < 96; ck++) {
        if (ck < 95) {   // prefetch next chunk
            int nk = ck + 1;
            int t = nk >> 5;
            int ce = (nk & 31) << 5;
            const __nv_bfloat16* ap = Asel[t] + (size_t)(m0 + lr) * 1024 + ce + lc;
            const __nv_bfloat16* wp = Wsel[t] + (size_t)(n0 + lr) * 1024 + ce + lc;
            va0 = *(const uint4*)ap; va1 = *(const uint4*)(ap + 8);
            vw0 = *(const uint4*)wp; vw1 = *(const uint4*)(wp + 8);
        }

        // compute on buf
        uint32_t aBase = sb + (uint32_t)(buf * 10240) + a_off;
        uint32_t bBase = sb + 20480u + (uint32_t)(buf * 10240) + b_off;
#pragma unroll
        for (int kk = 0; kk < 2; kk++) {
            uint32_t aF[4][4], bF[4][2];
#pragma unroll
            for (int i = 0; i < 4; i++)
                ldsm_x4(aF[i], aBase + (uint32_t)(i * 16 * 80) + (uint32_t)(kk * 32));
#pragma unroll
            for (int j = 0; j < 4; j++)
                ldsm_x2(bF[j], bBase + (uint32_t)(j * 8 * 80) + (uint32_t)(kk * 32));
#pragma unroll
            for (int i = 0; i < 4; i++)
#pragma unroll
                for (int j = 0; j < 4; j++)
                    mma16816(acc[i][j], aF[i][0], aF[i][1], aF[i][2], aF[i][3],
                             bF[j][0], bF[j][1]);
        }

        if (ck < 95) {   // store prefetch -> other buffer
            int nb = buf ^ 1;
            uint32_t so = (uint32_t)(nb * 10240 + lr * 80 + lc * 2);
            *(uint4*)(sm + so)          = va0;
            *(uint4*)(sm + so + 16)     = va1;
            *(uint4*)(sm + 20480 + so)      = vw0;
            *(uint4*)(sm + 20480 + so + 16) = vw1;
            __syncthreads();
            buf = nb;
        }
    }

    // ---- epilogue ----
    int qrow = lane >> 2;            // 0..7
    int qcol = (lane & 3) << 1;      // 0,2,4,6
    int region = (qkv != 0) ? (n0 >> 10) : 0;
    float* dst = O0;
    if (qkv != 0) dst = (region == 0) ? O0 : (region == 1) ? O1 : O2;

#pragma unroll
    for (int i = 0; i < 4; i++) {
#pragma unroll
        for (int hf = 0; hf < 2; hf++) {
            int m = m0 + warp_m * 64 + i * 16 + qrow + hf * 8;
            int bidx = m >> 11;
            int nrow = m & 2047;
#pragma unroll
            for (int j = 0; j < 4; j++) {
                int n = n0 + warp_n * 32 + j * 8 + qcol;
                float v0 = acc[i][j][hf * 2 + 0] + bias[n];
                float v1 = acc[i][j][hf * 2 + 1] + bias[n + 1];
                if (qkv == 0) {
                    *(float2*)(O0 + (size_t)m * 1024 + n) = make_float2(v0, v1);
                } else {
                    int h = (n & 1023) >> 6;
                    int hd = n & 63;
                    if (region < 2) {
                        int p = hd >> 1;
                        float c = g_cos[nrow * 32 + p], s = g_sin[nrow * 32 + p];
                        float w0 = v0 * c - v1 * s;
                        float w1 = v1 * c + v0 * s;
                        v0 = w0; v1 = w1;
                    }
                    *(float2*)(dst + ((size_t)(bidx * H_ + h) * N_ + nrow) * HD_ + hd) =
                        make_float2(v0, v1);
                }
            }
        }
    }
}

// ---------------------------------------------------------------------------
// Flash attention (unchanged, known-good): BM=128, BN=64, fp32 SIMT.
// ---------------------------------------------------------------------------
#define QT_OFF(d, c)  ((d)*128 + ((((c) ^ ((d) & 15))) << 2))
#define KT_OFF(d, c)  ((d)*64  + ((((c) ^ ((d) & 15))) << 2))
#define PS_STRIDE 68

__global__ void __launch_bounds__(256, 2) flash_kernel(float* __restrict__ Og) {
    extern __shared__ float sfm[];
    float* Qt = sfm;
    float* Kt = Qt + 64*128;
    float* Ps = Kt + 64*64;
    float* Vs = Ps + 128*PS_STRIDE;

    int tid = threadIdx.x;
    int tx = tid & 15, ty = tid >> 4;
    int mt = blockIdx.x;
    int bh = blockIdx.y;
    int m0 = mt * 128;

    const float* Qb = g_q + (size_t)bh * N_ * HD_;
    const float* Kb = g_k + (size_t)bh * N_ * HD_;
    const float* Vb = g_v + (size_t)bh * N_ * HD_;

    int r0 = (tid & 15) << 2;
    int d0 = (tid >> 4) << 2;

    {
        const float sc = 0.125f;
#pragma unroll
        for (int pass = 0; pass < 2; pass++) {
            int r = r0 + pass * 64;
            float4 v[4];
#pragma unroll
            for (int i = 0; i < 4; i++)
                v[i] = *(const float4*)(Qb + (size_t)(m0 + r + i) * HD_ + d0);
            const float* vp = (const float*)v;
#pragma unroll
            for (int j = 0; j < 4; j++) {
                float4 w = make_float4(vp[0*4+j]*sc, vp[1*4+j]*sc, vp[2*4+j]*sc, vp[3*4+j]*sc);
                *(float4*)&Qt[QT_OFF(d0 + j, (r >> 2))] = w;
            }
        }
    }

    float o[8][4] = {};
    float mrow[8], lrow[8];
#pragma unroll
    for (int i = 0; i < 8; i++) { mrow[i] = -1e30f; lrow[i] = 0.f; }

    int row_of[8];
#pragma unroll
    for (int i = 0; i < 8; i++)
        row_of[i] = (i >> 2) * 64 + (ty << 2) + (i & 3);

    int ntmax = 2 * mt + 1;
    for (int nt = 0; nt <= ntmax; nt++) {
        int n0k = nt * 64;
        __syncthreads();
        {
            float4 v[4];
#pragma unroll
            for (int i = 0; i < 4; i++)
                v[i] = *(const float4*)(Kb + (size_t)(n0k + r0 + i) * HD_ + d0);
            const float* vp = (const float*)v;
#pragma unroll
            for (int j = 0; j < 4; j++)
                *(float4*)&Kt[KT_OFF(d0 + j, (r0 >> 2))] =
                    make_float4(vp[0*4+j], vp[1*4+j], vp[2*4+j], vp[3*4+j]);
        }
#pragma unroll
        for (int t = 0; t < 4; t++) {
            int idx = tid + t * 256;
            int rr = idx >> 4, dd = (idx & 15) << 2;
            *(float4*)&Vs[rr * 64 + dd] = *(const float4*)(Vb + (size_t)(n0k + rr) * HD_ + dd);
        }
        __syncthreads();

        float s[8][4] = {};
#pragma unroll 8
        for (int d = 0; d < 64; d++) {
            float4 a0 = *(const float4*)&Qt[QT_OFF(d, ty)];
            float4 a1 = *(const float4*)&Qt[QT_OFF(d, 16 + ty)];
            float4 b  = *(const float4*)&Kt[KT_OFF(d, tx)];
            float aa[8] = {a0.x,a0.y,a0.z,a0.w,a1.x,a1.y,a1.z,a1.w};
            float bb[4] = {b.x,b.y,b.z,b.w};
#pragma unroll
            for (int i = 0; i < 8; i++)
#pragma unroll
                for (int j = 0; j < 4; j++)
                    s[i][j] += aa[i] * bb[j];
        }

        if (nt >= 2 * mt) {
#pragma unroll
            for (int i = 0; i < 8; i++)
#pragma unroll
                for (int j = 0; j < 4; j++)
                    if (n0k + (tx << 2) + j > m0 + row_of[i]) s[i][j] = -1e30f;
        }

#pragma unroll
        for (int i = 0; i < 8; i++) {
            float mx = fmaxf(fmaxf(s[i][0], s[i][1]), fmaxf(s[i][2], s[i][3]));
#pragma unroll
            for (int off = 1; off < 16; off <<= 1)
                mx = fmaxf(mx, __shfl_xor_sync(0xffffffffu, mx, off));
            float mn = fmaxf(mrow[i], mx);
            float al = __expf(mrow[i] - mn);
            mrow[i] = mn;
            float rs = 0.f;
#pragma unroll
            for (int j = 0; j < 4; j++) {
                float p = __expf(s[i][j] - mn);
                s[i][j] = p;
                rs += p;
            }
#pragma unroll
            for (int off = 1; off < 16; off <<= 1)
                rs += __shfl_xor_sync(0xffffffffu, rs, off);
            lrow[i] = lrow[i] * al + rs;
#pragma unroll
            for (int j = 0; j < 4; j++) o[i][j] *= al;
        }

#pragma unroll
        for (int i = 0; i < 8; i++)
            *(float4*)&Ps[row_of[i] * PS_STRIDE + (tx << 2)] =
                make_float4(s[i][0], s[i][1], s[i][2], s[i][3]);
        __syncthreads();

#pragma unroll 8
        for (int c = 0; c < 64; c++) {
            float4 b = *(const float4*)&Vs[c * 64 + (tx << 2)];
            float bb[4] = {b.x, b.y, b.z, b.w};
#pragma unroll
            for (int i = 0; i < 8; i++) {
                float a = Ps[row_of[i] * PS_STRIDE + c];
#pragma unroll
                for (int j = 0; j < 4; j++)
                    o[i][j] += a * bb[j];
            }
        }
    }

    int b_ = bh >> 4, h = bh & 15;
#pragma unroll
    for (int i = 0; i < 8; i++) {
        int m = m0 + row_of[i];
        float inv = 1.f / lrow[i];
        *(float4*)(Og + ((size_t)(b_ * N_ + m) * D_) + h * HD_ + (tx << 2)) =
            make_float4(o[i][0]*inv, o[i][1]*inv, o[i][2]*inv, o[i][3]*inv);
    }
}

// ---------------------------------------------------------------------------
extern "C" void kernel_launch(void* const* d_in, const int* in_sizes, int n_in,
                              void* d_out, int out_size)
{
    const float* x      = (const float*)d_in[0];
    const float* qkv_w  = (const float*)d_in[1];
    const float* qkv_b  = (const float*)d_in[2];
    const float* proj_w = (const float*)d_in[3];
    const float* proj_b = (const float*)d_in[4];
    float* out = (float*)d_out;

    float *q_p, *k_p, *v_p, *attn_p;
    cudaGetSymbolAddress((void**)&q_p,    g_q);
    cudaGetSymbolAddress((void**)&k_p,    g_k);
    cudaGetSymbolAddress((void**)&v_p,    g_v);
    cudaGetSymbolAddress((void**)&attn_p, g_attn);

    __nv_bfloat16 *xhi, *xlo, *wqh, *wql, *wph, *wpl, *ahi, *alo;
    cudaGetSymbolAddress((void**)&xhi, g_xhi);
    cudaGetSymbolAddress((void**)&xlo, g_xlo);
    cudaGetSymbolAddress((void**)&wqh, g_wqh);
    cudaGetSymbolAddress((void**)&wql, g_wql);
    cudaGetSymbolAddress((void**)&wph, g_wph);
    cudaGetSymbolAddress((void**)&wpl, g_wpl);
    cudaGetSymbolAddress((void**)&ahi, g_ahi);
    cudaGetSymbolAddress((void**)&alo, g_alo);

    const int FLASH_SMEM = (64*128 + 64*64 + 128*PS_STRIDE + 64*64) * 4;
    cudaFuncSetAttribute(flash_kernel, cudaFuncAttributeMaxDynamicSharedMemorySize, FLASH_SMEM);

    rope_table_kernel<<<(N_ * 32 + 255) / 256, 256>>>();

    {
        int n4 = 4096 * 1024 / 4;
        cvt_hilo_kernel<<<(n4 + 255) / 256, 256>>>((const float4*)x, (uint2*)xhi, (uint2*)xlo, n4);
    }
    {
        int n4 = 3072 * 1024 / 4;
        cvt_hilo_kernel<<<(n4 + 255) / 256, 256>>>((const float4*)qkv_w, (uint2*)wqh, (uint2*)wql, n4);
    }
    {
        int n4 = 1024 * 1024 / 4;
        cvt_hilo_kernel<<<(n4 + 255) / 256, 256>>>((const float4*)proj_w, (uint2*)wph, (uint2*)wpl, n4);
    }

    {   // QKV GEMM (mma.sync): M=4096, NC=3072
        dim3 grid(3072 / 128, 4096 / 128);
        mma_gemm_kernel<<<grid, 256>>>(xhi, xlo, wqh, wql, qkv_b, q_p, k_p, v_p, 1);
    }
    {   // flash attention
        dim3 grid(N_ / 128, B_ * H_);
        flash_kernel<<<grid, 256, FLASH_SMEM>>>(attn_p);
    }
    {   // convert attn output, then proj GEMM
        int n4 = 4096 * 1024 / 4;
        cvt_hilo_kernel<<<(n4 + 255) / 256, 256>>>((const float4*)attn_p, (uint2*)ahi, (uint2*)alo, n4);
        dim3 grid(1024 / 128, 4096 / 128);
        mma_gemm_kernel<<<grid, 256>>>(ahi, alo, wph, wpl, proj_b, out, nullptr, nullptr, 0);
    }
}

// round 9
// speedup vs baseline: 3.3577x; 2.3957x over previous
#include <cuda_runtime.h>
#include <cuda_bf16.h>
#include <cuda_fp16.h>
#include <math.h>
#include <stdint.h>

#define B_  2
#define N_  2048
#define D_  1024
#define H_  16
#define HD_ 64

// bf16/fp16 operand arrays
__device__ __nv_bfloat16 g_xhi[4096*1024], g_xlo[4096*1024];
__device__ __nv_bfloat16 g_wqh[3072*1024], g_wql[3072*1024];
__device__ __nv_bfloat16 g_wph[1024*1024], g_wpl[1024*1024];
__device__ __nv_bfloat16 g_qh[32*2048*64], g_ql[32*2048*64];
__device__ __nv_bfloat16 g_kh[32*2048*64], g_kl[32*2048*64];
__device__ __half        g_vh[32*2048*64];
__device__ __nv_bfloat16 g_ahi[4096*1024], g_alo[4096*1024];
__device__ float g_cos[N_*32];
__device__ float g_sin[N_*32];

// ---------------------------------------------------------------------------
// helpers (sm_80+ target-agnostic PTX only)
// ---------------------------------------------------------------------------
__device__ __forceinline__ uint32_t smem_u32(const void* p) {
    uint32_t a;
    asm("{ .reg .u64 t; cvta.to.shared.u64 t, %1; cvt.u32.u64 %0, t; }" : "=r"(a) : "l"(p));
    return a;
}
__device__ __forceinline__ void ldsm_x4(uint32_t* r, uint32_t addr) {
    asm volatile("ldmatrix.sync.aligned.m8n8.x4.shared.b16 {%0,%1,%2,%3}, [%4];"
        : "=r"(r[0]), "=r"(r[1]), "=r"(r[2]), "=r"(r[3]) : "r"(addr));
}
__device__ __forceinline__ void ldsm_x2(uint32_t* r, uint32_t addr) {
    asm volatile("ldmatrix.sync.aligned.m8n8.x2.shared.b16 {%0,%1}, [%2];"
        : "=r"(r[0]), "=r"(r[1]) : "r"(addr));
}
__device__ __forceinline__ void ldsm_x2_t(uint32_t* r, uint32_t addr) {
    asm volatile("ldmatrix.sync.aligned.m8n8.x2.trans.shared.b16 {%0,%1}, [%2];"
        : "=r"(r[0]), "=r"(r[1]) : "r"(addr));
}
__device__ __forceinline__ void mma_bf16(float* c, const uint32_t* a, const uint32_t* b) {
    asm volatile(
        "mma.sync.aligned.m16n8k16.row.col.f32.bf16.bf16.f32 "
        "{%0,%1,%2,%3}, {%4,%5,%6,%7}, {%8,%9}, {%0,%1,%2,%3};"
        : "+f"(c[0]), "+f"(c[1]), "+f"(c[2]), "+f"(c[3])
        : "r"(a[0]), "r"(a[1]), "r"(a[2]), "r"(a[3]), "r"(b[0]), "r"(b[1]));
}
__device__ __forceinline__ void mma_f16(float* c, const uint32_t* a, const uint32_t* b) {
    asm volatile(
        "mma.sync.aligned.m16n8k16.row.col.f32.f16.f16.f32 "
        "{%0,%1,%2,%3}, {%4,%5,%6,%7}, {%8,%9}, {%0,%1,%2,%3};"
        : "+f"(c[0]), "+f"(c[1]), "+f"(c[2]), "+f"(c[3])
        : "r"(a[0]), "r"(a[1]), "r"(a[2]), "r"(a[3]), "r"(b[0]), "r"(b[1]));
}
#define CP_ASYNC16(dst, src) \
    asm volatile("cp.async.cg.shared.global [%0], [%1], 16;" :: "r"(dst), "l"(src))
#define CP_COMMIT() asm volatile("cp.async.commit_group;" ::: "memory")
#define CP_WAIT0()  asm volatile("cp.async.wait_group 0;" ::: "memory")
#define CP_WAIT1()  asm volatile("cp.async.wait_group 1;" ::: "memory")

__device__ __forceinline__ uint32_t pack_h2(float a, float b) {
    __half2 h = __floats2half2_rn(a, b);
    return *reinterpret_cast<uint32_t*>(&h);
}
__device__ __forceinline__ uint32_t pack_bf2(float a, float b) {
    __nv_bfloat162 h = __floats2bfloat162_rn(a, b);
    return *reinterpret_cast<uint32_t*>(&h);
}

// ---------------------------------------------------------------------------
__global__ void rope_table_kernel() {
    int idx = blockIdx.x * blockDim.x + threadIdx.x;
    if (idx >= N_ * 32) return;
    int n = idx >> 5;
    int p = idx & 31;
    float invf = (float)pow(10000.0, -(double)(2 * p) / (double)HD_);
    double ang = (double)((float)n * invf);
    g_cos[idx] = (float)cos(ang);
    g_sin[idx] = (float)sin(ang);
}

__global__ void cvt_hilo_kernel(const float4* __restrict__ src,
                                uint2* __restrict__ hi, uint2* __restrict__ lo, int n4) {
    int i = blockIdx.x * blockDim.x + threadIdx.x;
    if (i >= n4) return;
    float4 v = src[i];
    __nv_bfloat162 h01 = __floats2bfloat162_rn(v.x, v.y);
    __nv_bfloat162 h23 = __floats2bfloat162_rn(v.z, v.w);
    float r0 = v.x - __low2float(h01), r1 = v.y - __high2float(h01);
    float r2 = v.z - __low2float(h23), r3 = v.w - __high2float(h23);
    __nv_bfloat162 l01 = __floats2bfloat162_rn(r0, r1);
    __nv_bfloat162 l23 = __floats2bfloat162_rn(r2, r3);
    uint2 hw, lw;
    hw.x = *reinterpret_cast<const unsigned*>(&h01);
    hw.y = *reinterpret_cast<const unsigned*>(&h23);
    lw.x = *reinterpret_cast<const unsigned*>(&l01);
    lw.y = *reinterpret_cast<const unsigned*>(&l23);
    hi[i] = hw;
    lo[i] = lw;
}

// ---------------------------------------------------------------------------
// Single-pass 3-term GEMM: C = A@W^T + bias. CTA 128x128, BK=32, 32 chunks,
// cp.async double-buffer (2 x 4 tiles x 10240B). 8 warps (2m x 4n).
// qkv=1: rope + split-store q/k (bf16 hi/lo), v (fp16). qkv=0: fp32 out.
// ---------------------------------------------------------------------------
__global__ void __launch_bounds__(256, 2)
mma_gemm_kernel(const __nv_bfloat16* __restrict__ Ah, const __nv_bfloat16* __restrict__ Al,
                const __nv_bfloat16* __restrict__ Wh, const __nv_bfloat16* __restrict__ Wl,
                const float* __restrict__ bias,
                __nv_bfloat16* __restrict__ QH, __nv_bfloat16* __restrict__ QL,
                __nv_bfloat16* __restrict__ KH, __nv_bfloat16* __restrict__ KL,
                __half* __restrict__ VH, float* __restrict__ OUT, int qkv)
{
    extern __shared__ char sm[];
    uint32_t sb = smem_u32(sm);

    int tid = threadIdx.x;
    int lane = tid & 31;
    int wid = tid >> 5;
    int warp_m = wid & 1;
    int warp_n = wid >> 1;
    int n0 = blockIdx.x * 128, m0 = blockIdx.y * 128;

    uint32_t a_off = (uint32_t)((warp_m * 64 + (lane & 15)) * 80 + ((lane >> 4) << 4));
    uint32_t b_off = (uint32_t)((warp_n * 32 + (lane & 7)) * 80 + (((lane >> 3) & 1) << 4));

    float acc[4][4][4];
#pragma unroll
    for (int i = 0; i < 4; i++)
#pragma unroll
        for (int j = 0; j < 4; j++)
#pragma unroll
            for (int q = 0; q < 4; q++) acc[i][j][q] = 0.f;

    const __nv_bfloat16* srcs[4];
    srcs[0] = Ah + (size_t)m0 * 1024;
    srcs[1] = Al + (size_t)m0 * 1024;
    srcs[2] = Wh + (size_t)n0 * 1024;
    srcs[3] = Wl + (size_t)n0 * 1024;

    // issue chunk 0 into buf 0
#pragma unroll
    for (int i = 0; i < 8; i++) {
        int c = tid + i * 256;
        int t = c >> 9, idx = c & 511, row = idx >> 2, c16 = idx & 3;
        CP_ASYNC16(sb + (uint32_t)(t * 10240 + row * 80 + c16 * 16),
                   srcs[t] + (size_t)row * 1024 + c16 * 8);
    }
    CP_COMMIT();

    int buf = 0;
#pragma unroll 1
    for (int ck = 0; ck < 32; ck++) {
        if (ck < 31) {
            int ce = (ck + 1) * 32;
            uint32_t db = sb + (uint32_t)((buf ^ 1) * 40960);
#pragma unroll
            for (int i = 0; i < 8; i++) {
                int c = tid + i * 256;
                int t = c >> 9, idx = c & 511, row = idx >> 2, c16 = idx & 3;
                CP_ASYNC16(db + (uint32_t)(t * 10240 + row * 80 + c16 * 16),
                           srcs[t] + (size_t)row * 1024 + ce + c16 * 8);
            }
            CP_COMMIT();
            CP_WAIT1();
        } else {
            CP_WAIT0();
        }
        __syncthreads();

        uint32_t base = sb + (uint32_t)(buf * 40960);
#pragma unroll
        for (int kk = 0; kk < 2; kk++) {
            uint32_t aFh[4][4], aFl[4][4];
#pragma unroll
            for (int i = 0; i < 4; i++) {
                ldsm_x4(aFh[i], base + a_off + (uint32_t)(i * 16 * 80 + kk * 32));
                ldsm_x4(aFl[i], base + 10240u + a_off + (uint32_t)(i * 16 * 80 + kk * 32));
            }
#pragma unroll
            for (int j = 0; j < 4; j++) {
                uint32_t bh2[2], bl2[2];
                ldsm_x2(bh2, base + 20480u + b_off + (uint32_t)(j * 8 * 80 + kk * 32));
                ldsm_x2(bl2, base + 30720u + b_off + (uint32_t)(j * 8 * 80 + kk * 32));
#pragma unroll
                for (int i = 0; i < 4; i++) {
                    mma_bf16(acc[i][j], aFh[i], bh2);
                    mma_bf16(acc[i][j], aFh[i], bl2);
                    mma_bf16(acc[i][j], aFl[i], bh2);
                }
            }
        }
        __syncthreads();
        buf ^= 1;
    }

    // ---- epilogue ----
    int qrow = lane >> 2;
    int qcol = (lane & 3) << 1;
    int region = (qkv != 0) ? (n0 >> 10) : 0;

#pragma unroll
    for (int i = 0; i < 4; i++) {
#pragma unroll
        for (int hf = 0; hf < 2; hf++) {
            int m = m0 + warp_m * 64 + i * 16 + qrow + hf * 8;
            int bidx = m >> 11;
            int nrow = m & 2047;
#pragma unroll
            for (int j = 0; j < 4; j++) {
                int n = n0 + warp_n * 32 + j * 8 + qcol;
                float v0 = acc[i][j][hf * 2 + 0] + bias[n];
                float v1 = acc[i][j][hf * 2 + 1] + bias[n + 1];
                if (qkv == 0) {
                    *(float2*)(OUT + (size_t)m * 1024 + n) = make_float2(v0, v1);
                } else {
                    int h = (n & 1023) >> 6;
                    int hd = n & 63;
                    size_t off = ((size_t)(bidx * H_ + h) * N_ + nrow) * HD_ + hd;
                    if (region == 2) {
                        *reinterpret_cast<uint32_t*>(VH + off) = pack_h2(v0, v1);
                    } else {
                        int p = hd >> 1;
                        float c = g_cos[nrow * 32 + p], s = g_sin[nrow * 32 + p];
                        float w0 = v0 * c - v1 * s;
                        float w1 = v1 * c + v0 * s;
                        if (region == 0) { w0 *= 0.125f; w1 *= 0.125f; }
                        __nv_bfloat162 hh = __floats2bfloat162_rn(w0, w1);
                        float l0 = w0 - __low2float(hh), l1 = w1 - __high2float(hh);
                        __nv_bfloat16* dh = (region == 0) ? QH : KH;
                        __nv_bfloat16* dl = (region == 0) ? QL : KL;
                        *reinterpret_cast<uint32_t*>(dh + off) =
                            *reinterpret_cast<uint32_t*>(&hh);
                        *reinterpret_cast<uint32_t*>(dl + off) = pack_bf2(l0, l1);
                    }
                }
            }
        }
    }
}

// ---------------------------------------------------------------------------
// Tensor-core causal flash attention. BM=128 (8 warps x 16 rows), BN=64.
// S: 3-term bf16 (QhKh + QhKl + QlKh). P@V: fp16 single-pass, P frags reuse
// S accumulator registers (FA2 layout identity).
// smem: QHs 18432 | QLs 18432 | KHs 9216 | KLs 9216 | VHs 9216 = 64512 B.
// Output written directly as bf16 hi/lo for the proj GEMM.
// ---------------------------------------------------------------------------
__global__ void __launch_bounds__(256) flash_mma_kernel(
    const __nv_bfloat16* __restrict__ QH, const __nv_bfloat16* __restrict__ QL,
    const __nv_bfloat16* __restrict__ KH, const __nv_bfloat16* __restrict__ KL,
    const __half* __restrict__ VH,
    __nv_bfloat16* __restrict__ AHI, __nv_bfloat16* __restrict__ ALO)
{
    extern __shared__ char sm[];
    uint32_t sb = smem_u32(sm);
    const uint32_t QHs = 0, QLs = 18432, KHs = 36864, KLs = 46080, VHs = 55296;

    int tid = threadIdx.x;
    int lane = tid & 31;
    int w = tid >> 5;
    int mt = blockIdx.x, bh = blockIdx.y;
    int m0 = mt * 128;
    size_t bhoff = (size_t)bh * N_ * HD_;

    // stage Q (hi+lo) via cp.async: 2 tiles x 128 rows x 8 chunks
#pragma unroll
    for (int i = 0; i < 8; i++) {
        int c = tid + i * 256;
        int t = c >> 10, idx = c & 1023, row = idx >> 3, c16 = idx & 7;
        const __nv_bfloat16* src = (t ? QL : QH) + bhoff + (size_t)(m0 + row) * 64 + c16 * 8;
        CP_ASYNC16(sb + (t ? QLs : QHs) + (uint32_t)(row * 144 + c16 * 16), src);
    }
    CP_COMMIT();
    CP_WAIT0();
    __syncthreads();

    float o[8][4];
#pragma unroll
    for (int j = 0; j < 8; j++)
#pragma unroll
        for (int q = 0; q < 4; q++) o[j][q] = 0.f;
    float mrow0 = -1e30f, mrow1 = -1e30f, lrow0 = 0.f, lrow1 = 0.f;

    int q0w = m0 + w * 16;
    uint32_t qh_base = sb + QHs + (uint32_t)((w * 16 + (lane & 15)) * 144 + ((lane >> 4) << 4));
    uint32_t ql_base = qh_base + (QLs - QHs);
    uint32_t kb_off = (uint32_t)((lane & 7) * 144 + (((lane >> 3) & 1) << 4));
    uint32_t vb_off = (uint32_t)((lane & 15) * 144);

    int ntmax = 2 * mt + 1;
#pragma unroll 1
    for (int nt = 0; nt <= ntmax; nt++) {
        int kv0 = nt * 64;
        __syncthreads();   // prior iter done reading K/V
        // load K hi/lo + V (3 tiles x 64 rows x 8 chunks = 1536)
#pragma unroll
        for (int i = 0; i < 6; i++) {
            int c = tid + i * 256;
            int t = c >> 9, idx = c & 511, row = idx >> 3, c16 = idx & 7;
            const void* src;
            uint32_t dst;
            if (t == 0)      { src = KH + bhoff + (size_t)(kv0 + row) * 64 + c16 * 8; dst = sb + KHs; }
            else if (t == 1) { src = KL + bhoff + (size_t)(kv0 + row) * 64 + c16 * 8; dst = sb + KLs; }
            else             { src = VH + bhoff + (size_t)(kv0 + row) * 64 + c16 * 8; dst = sb + VHs; }
            CP_ASYNC16(dst + (uint32_t)(row * 144 + c16 * 16), src);
        }
        CP_COMMIT();
        CP_WAIT0();
        __syncthreads();

        if (kv0 <= q0w + 15) {
            float s[8][4];
#pragma unroll
            for (int j = 0; j < 8; j++)
#pragma unroll
                for (int q = 0; q < 4; q++) s[j][q] = 0.f;

#pragma unroll
            for (int kt = 0; kt < 4; kt++) {
                uint32_t ah[4], al[4];
                ldsm_x4(ah, qh_base + (uint32_t)(kt * 32));
                ldsm_x4(al, ql_base + (uint32_t)(kt * 32));
#pragma unroll
                for (int j = 0; j < 8; j++) {
                    uint32_t bh2[2], bl2[2];
                    ldsm_x2(bh2, sb + KHs + kb_off + (uint32_t)(j * 8 * 144 + kt * 32));
                    ldsm_x2(bl2, sb + KLs + kb_off + (uint32_t)(j * 8 * 144 + kt * 32));
                    mma_bf16(s[j], ah, bh2);
                    mma_bf16(s[j], ah, bl2);
                    mma_bf16(s[j], al, bh2);
                }
            }

            if (kv0 + 63 > q0w) {   // causal mask near diagonal
                int r0g = q0w + (lane >> 2);
                int r1g = r0g + 8;
#pragma unroll
                for (int j = 0; j < 8; j++) {
                    int cg = kv0 + 8 * j + ((lane & 3) << 1);
                    if (cg > r0g)     s[j][0] = -1e30f;
                    if (cg + 1 > r0g) s[j][1] = -1e30f;
                    if (cg > r1g)     s[j][2] = -1e30f;
                    if (cg + 1 > r1g) s[j][3] = -1e30f;
                }
            }

            // online softmax (rows r0 = lane>>2, r1 = r0+8; 4-lane groups)
            float mx0 = -1e30f, mx1 = -1e30f;
#pragma unroll
            for (int j = 0; j < 8; j++) {
                mx0 = fmaxf(mx0, fmaxf(s[j][0], s[j][1]));
                mx1 = fmaxf(mx1, fmaxf(s[j][2], s[j][3]));
            }
            mx0 = fmaxf(mx0, __shfl_xor_sync(0xffffffffu, mx0, 1));
            mx0 = fmaxf(mx0, __shfl_xor_sync(0xffffffffu, mx0, 2));
            mx1 = fmaxf(mx1, __shfl_xor_sync(0xffffffffu, mx1, 1));
            mx1 = fmaxf(mx1, __shfl_xor_sync(0xffffffffu, mx1, 2));
            float mn0 = fmaxf(mrow0, mx0), mn1 = fmaxf(mrow1, mx1);
            float al0 = __expf(mrow0 - mn0), al1 = __expf(mrow1 - mn1);
            mrow0 = mn0; mrow1 = mn1;
            float rs0 = 0.f, rs1 = 0.f;
#pragma unroll
            for (int j = 0; j < 8; j++) {
                s[j][0] = __expf(s[j][0] - mn0);
                s[j][1] = __expf(s[j][1] - mn0);
                s[j][2] = __expf(s[j][2] - mn1);
                s[j][3] = __expf(s[j][3] - mn1);
                rs0 += s[j][0] + s[j][1];
                rs1 += s[j][2] + s[j][3];
            }
            rs0 += __shfl_xor_sync(0xffffffffu, rs0, 1);
            rs0 += __shfl_xor_sync(0xffffffffu, rs0, 2);
            rs1 += __shfl_xor_sync(0xffffffffu, rs1, 1);
            rs1 += __shfl_xor_sync(0xffffffffu, rs1, 2);
            lrow0 = lrow0 * al0 + rs0;
            lrow1 = lrow1 * al1 + rs1;
#pragma unroll
            for (int j = 0; j < 8; j++) {
                o[j][0] *= al0; o[j][1] *= al0;
                o[j][2] *= al1; o[j][3] *= al1;
            }

            // P fragments (fp16) directly from S accumulators
            uint32_t pf[4][4];
#pragma unroll
            for (int t = 0; t < 4; t++) {
                pf[t][0] = pack_h2(s[2*t][0],   s[2*t][1]);
                pf[t][1] = pack_h2(s[2*t][2],   s[2*t][3]);
                pf[t][2] = pack_h2(s[2*t+1][0], s[2*t+1][1]);
                pf[t][3] = pack_h2(s[2*t+1][2], s[2*t+1][3]);
            }
            // O += P @ V
#pragma unroll
            for (int t = 0; t < 4; t++) {
#pragma unroll
                for (int j = 0; j < 8; j++) {
                    uint32_t vf[2];
                    ldsm_x2_t(vf, sb + VHs + vb_off + (uint32_t)(t * 16 * 144 + j * 16));
                    mma_f16(o[j], pf[t], vf);
                }
            }
        }
    }

    // epilogue: write bf16 hi/lo attention output [token][h*64+hd]
    int b_ = bh >> 4, h = bh & 15;
    float inv0 = 1.f / lrow0, inv1 = 1.f / lrow1;
#pragma unroll
    for (int rr = 0; rr < 2; rr++) {
        int row = q0w + (lane >> 2) + rr * 8;
        float inv = rr ? inv1 : inv0;
        size_t base = (size_t)(b_ * N_ + row) * D_ + h * 64;
#pragma unroll
        for (int j = 0; j < 8; j++) {
            int hd = 8 * j + ((lane & 3) << 1);
            float v0 = o[j][rr * 2 + 0] * inv;
            float v1 = o[j][rr * 2 + 1] * inv;
            __nv_bfloat162 hh = __floats2bfloat162_rn(v0, v1);
            float l0 = v0 - __low2float(hh), l1 = v1 - __high2float(hh);
            *reinterpret_cast<uint32_t*>(AHI + base + hd) = *reinterpret_cast<uint32_t*>(&hh);
            *reinterpret_cast<uint32_t*>(ALO + base + hd) = pack_bf2(l0, l1);
        }
    }
}

// ---------------------------------------------------------------------------
extern "C" void kernel_launch(void* const* d_in, const int* in_sizes, int n_in,
                              void* d_out, int out_size)
{
    const float* x      = (const float*)d_in[0];
    const float* qkv_w  = (const float*)d_in[1];
    const float* qkv_b  = (const float*)d_in[2];
    const float* proj_w = (const float*)d_in[3];
    const float* proj_b = (const float*)d_in[4];
    float* out = (float*)d_out;

    __nv_bfloat16 *xhi, *xlo, *wqh, *wql, *wph, *wpl, *ahi, *alo;
    __nv_bfloat16 *qh, *ql, *kh, *kl;
    __half *vh;
    cudaGetSymbolAddress((void**)&xhi, g_xhi);
    cudaGetSymbolAddress((void**)&xlo, g_xlo);
    cudaGetSymbolAddress((void**)&wqh, g_wqh);
    cudaGetSymbolAddress((void**)&wql, g_wql);
    cudaGetSymbolAddress((void**)&wph, g_wph);
    cudaGetSymbolAddress((void**)&wpl, g_wpl);
    cudaGetSymbolAddress((void**)&ahi, g_ahi);
    cudaGetSymbolAddress((void**)&alo, g_alo);
    cudaGetSymbolAddress((void**)&qh,  g_qh);
    cudaGetSymbolAddress((void**)&ql,  g_ql);
    cudaGetSymbolAddress((void**)&kh,  g_kh);
    cudaGetSymbolAddress((void**)&kl,  g_kl);
    cudaGetSymbolAddress((void**)&vh,  g_vh);

    const int GEMM_SMEM  = 81920;
    const int FLASH_SMEM = 64512;
    cudaFuncSetAttribute(mma_gemm_kernel,  cudaFuncAttributeMaxDynamicSharedMemorySize, GEMM_SMEM);
    cudaFuncSetAttribute(flash_mma_kernel, cudaFuncAttributeMaxDynamicSharedMemorySize, FLASH_SMEM);

    rope_table_kernel<<<(N_ * 32 + 255) / 256, 256>>>();

    {
        int n4 = 4096 * 1024 / 4;
        cvt_hilo_kernel<<<(n4 + 255) / 256, 256>>>((const float4*)x, (uint2*)xhi, (uint2*)xlo, n4);
    }
    {
        int n4 = 3072 * 1024 / 4;
        cvt_hilo_kernel<<<(n4 + 255) / 256, 256>>>((const float4*)qkv_w, (uint2*)wqh, (uint2*)wql, n4);
    }
    {
        int n4 = 1024 * 1024 / 4;
        cvt_hilo_kernel<<<(n4 + 255) / 256, 256>>>((const float4*)proj_w, (uint2*)wph, (uint2*)wpl, n4);
    }

    {   // QKV GEMM: M=4096, NC=3072 -> q/k (bf16 hi/lo, roped, scaled) + v (fp16)
        dim3 grid(3072 / 128, 4096 / 128);
        mma_gemm_kernel<<<grid, 256, GEMM_SMEM>>>(xhi, xlo, wqh, wql, qkv_b,
                                                  qh, ql, kh, kl, vh, nullptr, 1);
    }
    {   // flash attention -> ahi/alo
        dim3 grid(N_ / 128, B_ * H_);
        flash_mma_kernel<<<grid, 256, FLASH_SMEM>>>(qh, ql, kh, kl, vh, ahi, alo);
    }
    {   // proj GEMM: M=4096, NC=1024 -> out
        dim3 grid(1024 / 128, 4096 / 128);
        mma_gemm_kernel<<<grid, 256, GEMM_SMEM>>>(ahi, alo, wph, wpl, proj_b,
                                                  nullptr, nullptr, nullptr, nullptr, nullptr, out, 0);
    }
}

// round 10
// speedup vs baseline: 3.3671x; 1.0028x over previous
#include <cuda_runtime.h>
#include <cuda_bf16.h>
#include <cuda_fp16.h>
#include <math.h>
#include <stdint.h>

#define B_  2
#define N_  2048
#define D_  1024
#define H_  16
#define HD_ 64

// bf16/fp16 operand arrays
__device__ __nv_bfloat16 g_xhi[4096*1024], g_xlo[4096*1024];
__device__ __nv_bfloat16 g_wqh[3072*1024], g_wql[3072*1024];
__device__ __nv_bfloat16 g_wph[1024*1024], g_wpl[1024*1024];
__device__ __nv_bfloat16 g_qh[32*2048*64], g_ql[32*2048*64];
__device__ __nv_bfloat16 g_kh[32*2048*64], g_kl[32*2048*64];
__device__ __half        g_vh[32*2048*64];
__device__ __nv_bfloat16 g_ahi[4096*1024], g_alo[4096*1024];
__device__ float g_cos[N_*32];
__device__ float g_sin[N_*32];

// ---------------------------------------------------------------------------
// helpers (sm_80+ target-agnostic PTX only)
// ---------------------------------------------------------------------------
__device__ __forceinline__ uint32_t smem_u32(const void* p) {
    uint32_t a;
    asm("{ .reg .u64 t; cvta.to.shared.u64 t, %1; cvt.u32.u64 %0, t; }" : "=r"(a) : "l"(p));
    return a;
}
__device__ __forceinline__ void ldsm_x4(uint32_t* r, uint32_t addr) {
    asm volatile("ldmatrix.sync.aligned.m8n8.x4.shared.b16 {%0,%1,%2,%3}, [%4];"
        : "=r"(r[0]), "=r"(r[1]), "=r"(r[2]), "=r"(r[3]) : "r"(addr));
}
__device__ __forceinline__ void ldsm_x2(uint32_t* r, uint32_t addr) {
    asm volatile("ldmatrix.sync.aligned.m8n8.x2.shared.b16 {%0,%1}, [%2];"
        : "=r"(r[0]), "=r"(r[1]) : "r"(addr));
}
__device__ __forceinline__ void ldsm_x2_t(uint32_t* r, uint32_t addr) {
    asm volatile("ldmatrix.sync.aligned.m8n8.x2.trans.shared.b16 {%0,%1}, [%2];"
        : "=r"(r[0]), "=r"(r[1]) : "r"(addr));
}
__device__ __forceinline__ void mma_bf16(float* c, const uint32_t* a, const uint32_t* b) {
    asm volatile(
        "mma.sync.aligned.m16n8k16.row.col.f32.bf16.bf16.f32 "
        "{%0,%1,%2,%3}, {%4,%5,%6,%7}, {%8,%9}, {%0,%1,%2,%3};"
        : "+f"(c[0]), "+f"(c[1]), "+f"(c[2]), "+f"(c[3])
        : "r"(a[0]), "r"(a[1]), "r"(a[2]), "r"(a[3]), "r"(b[0]), "r"(b[1]));
}
__device__ __forceinline__ void mma_f16(float* c, const uint32_t* a, const uint32_t* b) {
    asm volatile(
        "mma.sync.aligned.m16n8k16.row.col.f32.f16.f16.f32 "
        "{%0,%1,%2,%3}, {%4,%5,%6,%7}, {%8,%9}, {%0,%1,%2,%3};"
        : "+f"(c[0]), "+f"(c[1]), "+f"(c[2]), "+f"(c[3])
        : "r"(a[0]), "r"(a[1]), "r"(a[2]), "r"(a[3]), "r"(b[0]), "r"(b[1]));
}
#define CP_ASYNC16(dst, src) \
    asm volatile("cp.async.cg.shared.global [%0], [%1], 16;" :: "r"(dst), "l"(src))
#define CP_COMMIT() asm volatile("cp.async.commit_group;" ::: "memory")
#define CP_WAIT0()  asm volatile("cp.async.wait_group 0;" ::: "memory")
#define CP_WAIT1()  asm volatile("cp.async.wait_group 1;" ::: "memory")

__device__ __forceinline__ uint32_t pack_h2(float a, float b) {
    __half2 h = __floats2half2_rn(a, b);
    return *reinterpret_cast<uint32_t*>(&h);
}
__device__ __forceinline__ uint32_t pack_bf2(float a, float b) {
    __nv_bfloat162 h = __floats2bfloat162_rn(a, b);
    return *reinterpret_cast<uint32_t*>(&h);
}

// ---------------------------------------------------------------------------
__global__ void rope_table_kernel() {
    int idx = blockIdx.x * blockDim.x + threadIdx.x;
    if (idx >= N_ * 32) return;
    int n = idx >> 5;
    int p = idx & 31;
    float invf = (float)pow(10000.0, -(double)(2 * p) / (double)HD_);
    double ang = (double)((float)n * invf);
    g_cos[idx] = (float)cos(ang);
    g_sin[idx] = (float)sin(ang);
}

__global__ void cvt_hilo_kernel(const float4* __restrict__ src,
                                uint2* __restrict__ hi, uint2* __restrict__ lo, int n4) {
    int i = blockIdx.x * blockDim.x + threadIdx.x;
    if (i >= n4) return;
    float4 v = src[i];
    __nv_bfloat162 h01 = __floats2bfloat162_rn(v.x, v.y);
    __nv_bfloat162 h23 = __floats2bfloat162_rn(v.z, v.w);
    float r0 = v.x - __low2float(h01), r1 = v.y - __high2float(h01);
    float r2 = v.z - __low2float(h23), r3 = v.w - __high2float(h23);
    __nv_bfloat162 l01 = __floats2bfloat162_rn(r0, r1);
    __nv_bfloat162 l23 = __floats2bfloat162_rn(r2, r3);
    uint2 hw, lw;
    hw.x = *reinterpret_cast<const unsigned*>(&h01);
    hw.y = *reinterpret_cast<const unsigned*>(&h23);
    lw.x = *reinterpret_cast<const unsigned*>(&l01);
    lw.y = *reinterpret_cast<const unsigned*>(&l23);
    hi[i] = hw;
    lo[i] = lw;
}

// ---------------------------------------------------------------------------
// Single-pass 3-term GEMM (unchanged from R9 passing version).
// ---------------------------------------------------------------------------
__global__ void __launch_bounds__(256, 2)
mma_gemm_kernel(const __nv_bfloat16* __restrict__ Ah, const __nv_bfloat16* __restrict__ Al,
                const __nv_bfloat16* __restrict__ Wh, const __nv_bfloat16* __restrict__ Wl,
                const float* __restrict__ bias,
                __nv_bfloat16* __restrict__ QH, __nv_bfloat16* __restrict__ QL,
                __nv_bfloat16* __restrict__ KH, __nv_bfloat16* __restrict__ KL,
                __half* __restrict__ VH, float* __restrict__ OUT, int qkv)
{
    extern __shared__ char sm[];
    uint32_t sb = smem_u32(sm);

    int tid = threadIdx.x;
    int lane = tid & 31;
    int wid = tid >> 5;
    int warp_m = wid & 1;
    int warp_n = wid >> 1;
    int n0 = blockIdx.x * 128, m0 = blockIdx.y * 128;

    uint32_t a_off = (uint32_t)((warp_m * 64 + (lane & 15)) * 80 + ((lane >> 4) << 4));
    uint32_t b_off = (uint32_t)((warp_n * 32 + (lane & 7)) * 80 + (((lane >> 3) & 1) << 4));

    float acc[4][4][4];
#pragma unroll
    for (int i = 0; i < 4; i++)
#pragma unroll
        for (int j = 0; j < 4; j++)
#pragma unroll
            for (int q = 0; q < 4; q++) acc[i][j][q] = 0.f;

    const __nv_bfloat16* srcs[4];
    srcs[0] = Ah + (size_t)m0 * 1024;
    srcs[1] = Al + (size_t)m0 * 1024;
    srcs[2] = Wh + (size_t)n0 * 1024;
    srcs[3] = Wl + (size_t)n0 * 1024;

#pragma unroll
    for (int i = 0; i < 8; i++) {
        int c = tid + i * 256;
        int t = c >> 9, idx = c & 511, row = idx >> 2, c16 = idx & 3;
        CP_ASYNC16(sb + (uint32_t)(t * 10240 + row * 80 + c16 * 16),
                   srcs[t] + (size_t)row * 1024 + c16 * 8);
    }
    CP_COMMIT();

    int buf = 0;
#pragma unroll 1
    for (int ck = 0; ck < 32; ck++) {
        if (ck < 31) {
            int ce = (ck + 1) * 32;
            uint32_t db = sb + (uint32_t)((buf ^ 1) * 40960);
#pragma unroll
            for (int i = 0; i < 8; i++) {
                int c = tid + i * 256;
                int t = c >> 9, idx = c & 511, row = idx >> 2, c16 = idx & 3;
                CP_ASYNC16(db + (uint32_t)(t * 10240 + row * 80 + c16 * 16),
                           srcs[t] + (size_t)row * 1024 + ce + c16 * 8);
            }
            CP_COMMIT();
            CP_WAIT1();
        } else {
            CP_WAIT0();
        }
        __syncthreads();

        uint32_t base = sb + (uint32_t)(buf * 40960);
#pragma unroll
        for (int kk = 0; kk < 2; kk++) {
            uint32_t aFh[4][4], aFl[4][4];
#pragma unroll
            for (int i = 0; i < 4; i++) {
                ldsm_x4(aFh[i], base + a_off + (uint32_t)(i * 16 * 80 + kk * 32));
                ldsm_x4(aFl[i], base + 10240u + a_off + (uint32_t)(i * 16 * 80 + kk * 32));
            }
#pragma unroll
            for (int j = 0; j < 4; j++) {
                uint32_t bh2[2], bl2[2];
                ldsm_x2(bh2, base + 20480u + b_off + (uint32_t)(j * 8 * 80 + kk * 32));
                ldsm_x2(bl2, base + 30720u + b_off + (uint32_t)(j * 8 * 80 + kk * 32));
#pragma unroll
                for (int i = 0; i < 4; i++) {
                    mma_bf16(acc[i][j], aFh[i], bh2);
                    mma_bf16(acc[i][j], aFh[i], bl2);
                    mma_bf16(acc[i][j], aFl[i], bh2);
                }
            }
        }
        __syncthreads();
        buf ^= 1;
    }

    // ---- epilogue ----
    int qrow = lane >> 2;
    int qcol = (lane & 3) << 1;
    int region = (qkv != 0) ? (n0 >> 10) : 0;

#pragma unroll
    for (int i = 0; i < 4; i++) {
#pragma unroll
        for (int hf = 0; hf < 2; hf++) {
            int m = m0 + warp_m * 64 + i * 16 + qrow + hf * 8;
            int bidx = m >> 11;
            int nrow = m & 2047;
#pragma unroll
            for (int j = 0; j < 4; j++) {
                int n = n0 + warp_n * 32 + j * 8 + qcol;
                float v0 = acc[i][j][hf * 2 + 0] + bias[n];
                float v1 = acc[i][j][hf * 2 + 1] + bias[n + 1];
                if (qkv == 0) {
                    *(float2*)(OUT + (size_t)m * 1024 + n) = make_float2(v0, v1);
                } else {
                    int h = (n & 1023) >> 6;
                    int hd = n & 63;
                    size_t off = ((size_t)(bidx * H_ + h) * N_ + nrow) * HD_ + hd;
                    if (region == 2) {
                        *reinterpret_cast<uint32_t*>(VH + off) = pack_h2(v0, v1);
                    } else {
                        int p = hd >> 1;
                        float c = g_cos[nrow * 32 + p], s = g_sin[nrow * 32 + p];
                        float w0 = v0 * c - v1 * s;
                        float w1 = v1 * c + v0 * s;
                        if (region == 0) { w0 *= 0.125f; w1 *= 0.125f; }
                        __nv_bfloat162 hh = __floats2bfloat162_rn(w0, w1);
                        float l0 = w0 - __low2float(hh), l1 = w1 - __high2float(hh);
                        __nv_bfloat16* dh = (region == 0) ? QH : KH;
                        __nv_bfloat16* dl = (region == 0) ? QL : KL;
                        *reinterpret_cast<uint32_t*>(dh + off) =
                            *reinterpret_cast<uint32_t*>(&hh);
                        *reinterpret_cast<uint32_t*>(dl + off) = pack_bf2(l0, l1);
                    }
                }
            }
        }
    }
}

// ---------------------------------------------------------------------------
// Tensor-core causal flash attention, double-buffered K/V (one-tile lookahead).
// smem: QHs 18432 | QLs 18432 | KV buf x2 (KH 9216 | KL 9216 | V 9216) = 92160 B.
// ---------------------------------------------------------------------------
__global__ void __launch_bounds__(256) flash_mma_kernel(
    const __nv_bfloat16* __restrict__ QH, const __nv_bfloat16* __restrict__ QL,
    const __nv_bfloat16* __restrict__ KH, const __nv_bfloat16* __restrict__ KL,
    const __half* __restrict__ VH,
    __nv_bfloat16* __restrict__ AHI, __nv_bfloat16* __restrict__ ALO)
{
    extern __shared__ char sm[];
    uint32_t sb = smem_u32(sm);
    const uint32_t QHs = 0, QLs = 18432, KVs = 36864;   // + buf*27648

    int tid = threadIdx.x;
    int lane = tid & 31;
    int w = tid >> 5;
    int mt = blockIdx.x, bh = blockIdx.y;
    int m0 = mt * 128;
    size_t bhoff = (size_t)bh * N_ * HD_;
    int ntmax = 2 * mt + 1;

    // prologue group 0: Q (hi+lo) + KV tile 0
#pragma unroll
    for (int i = 0; i < 8; i++) {
        int c = tid + i * 256;
        int t = c >> 10, idx = c & 1023, row = idx >> 3, c16 = idx & 7;
        const __nv_bfloat16* src = (t ? QL : QH) + bhoff + (size_t)(m0 + row) * 64 + c16 * 8;
        CP_ASYNC16(sb + (t ? QLs : QHs) + (uint32_t)(row * 144 + c16 * 16), src);
    }
    {
        uint32_t kv = sb + KVs;
#pragma unroll
        for (int i = 0; i < 6; i++) {
            int c = tid + i * 256;
            int t = c >> 9, idx = c & 511, row = idx >> 3, c16 = idx & 7;
            const void* src;
            if (t == 0)      src = KH + bhoff + (size_t)row * 64 + c16 * 8;
            else if (t == 1) src = KL + bhoff + (size_t)row * 64 + c16 * 8;
            else             src = VH + bhoff + (size_t)row * 64 + c16 * 8;
            CP_ASYNC16(kv + (uint32_t)(t * 9216 + row * 144 + c16 * 16), src);
        }
    }
    CP_COMMIT();
    // prologue group 1: KV tile 1 (ntmax >= 1 always)
    {
        uint32_t kv = sb + KVs + 27648u;
#pragma unroll
        for (int i = 0; i < 6; i++) {
            int c = tid + i * 256;
            int t = c >> 9, idx = c & 511, row = idx >> 3, c16 = idx & 7;
            const void* src;
            if (t == 0)      src = KH + bhoff + (size_t)(64 + row) * 64 + c16 * 8;
            else if (t == 1) src = KL + bhoff + (size_t)(64 + row) * 64 + c16 * 8;
            else             src = VH + bhoff + (size_t)(64 + row) * 64 + c16 * 8;
            CP_ASYNC16(kv + (uint32_t)(t * 9216 + row * 144 + c16 * 16), src);
        }
    }
    CP_COMMIT();

    float o[8][4];
#pragma unroll
    for (int j = 0; j < 8; j++)
#pragma unroll
        for (int q = 0; q < 4; q++) o[j][q] = 0.f;
    float mrow0 = -1e30f, mrow1 = -1e30f, lrow0 = 0.f, lrow1 = 0.f;

    int q0w = m0 + w * 16;
    uint32_t qh_base = sb + QHs + (uint32_t)((w * 16 + (lane & 15)) * 144 + ((lane >> 4) << 4));
    uint32_t ql_base = qh_base + (QLs - QHs);
    uint32_t kb_off = (uint32_t)((lane & 7) * 144 + (((lane >> 3) & 1) << 4));
    uint32_t vb_off = (uint32_t)((lane & 15) * 144);

#pragma unroll 1
    for (int nt = 0; nt <= ntmax; nt++) {
        int kv0 = nt * 64;
        if (nt < ntmax) { CP_WAIT1(); } else { CP_WAIT0(); }
        __syncthreads();   // data for nt visible to all threads

        uint32_t kvb = sb + KVs + (uint32_t)((nt & 1) * 27648);

        if (kv0 <= q0w + 15) {
            float s[8][4];
#pragma unroll
            for (int j = 0; j < 8; j++)
#pragma unroll
                for (int q = 0; q < 4; q++) s[j][q] = 0.f;

#pragma unroll
            for (int kt = 0; kt < 4; kt++) {
                uint32_t ah[4], al[4];
                ldsm_x4(ah, qh_base + (uint32_t)(kt * 32));
                ldsm_x4(al, ql_base + (uint32_t)(kt * 32));
#pragma unroll
                for (int j = 0; j < 8; j++) {
                    uint32_t bh2[2], bl2[2];
                    ldsm_x2(bh2, kvb + kb_off + (uint32_t)(j * 8 * 144 + kt * 32));
                    ldsm_x2(bl2, kvb + 9216u + kb_off + (uint32_t)(j * 8 * 144 + kt * 32));
                    mma_bf16(s[j], ah, bh2);
                    mma_bf16(s[j], ah, bl2);
                    mma_bf16(s[j], al, bh2);
                }
            }

            if (kv0 + 63 > q0w) {
                int r0g = q0w + (lane >> 2);
                int r1g = r0g + 8;
#pragma unroll
                for (int j = 0; j < 8; j++) {
                    int cg = kv0 + 8 * j + ((lane & 3) << 1);
                    if (cg > r0g)     s[j][0] = -1e30f;
                    if (cg + 1 > r0g) s[j][1] = -1e30f;
                    if (cg > r1g)     s[j][2] = -1e30f;
                    if (cg + 1 > r1g) s[j][3] = -1e30f;
                }
            }

            float mx0 = -1e30f, mx1 = -1e30f;
#pragma unroll
            for (int j = 0; j < 8; j++) {
                mx0 = fmaxf(mx0, fmaxf(s[j][0], s[j][1]));
                mx1 = fmaxf(mx1, fmaxf(s[j][2], s[j][3]));
            }
            mx0 = fmaxf(mx0, __shfl_xor_sync(0xffffffffu, mx0, 1));
            mx0 = fmaxf(mx0, __shfl_xor_sync(0xffffffffu, mx0, 2));
            mx1 = fmaxf(mx1, __shfl_xor_sync(0xffffffffu, mx1, 1));
            mx1 = fmaxf(mx1, __shfl_xor_sync(0xffffffffu, mx1, 2));
            float mn0 = fmaxf(mrow0, mx0), mn1 = fmaxf(mrow1, mx1);
            float al0 = __expf(mrow0 - mn0), al1 = __expf(mrow1 - mn1);
            mrow0 = mn0; mrow1 = mn1;
            float rs0 = 0.f, rs1 = 0.f;
#pragma unroll
            for (int j = 0; j < 8; j++) {
                s[j][0] = __expf(s[j][0] - mn0);
                s[j][1] = __expf(s[j][1] - mn0);
                s[j][2] = __expf(s[j][2] - mn1);
                s[j][3] = __expf(s[j][3] - mn1);
                rs0 += s[j][0] + s[j][1];
                rs1 += s[j][2] + s[j][3];
            }
            rs0 += __shfl_xor_sync(0xffffffffu, rs0, 1);
            rs0 += __shfl_xor_sync(0xffffffffu, rs0, 2);
            rs1 += __shfl_xor_sync(0xffffffffu, rs1, 1);
            rs1 += __shfl_xor_sync(0xffffffffu, rs1, 2);
            lrow0 = lrow0 * al0 + rs0;
            lrow1 = lrow1 * al1 + rs1;
#pragma unroll
            for (int j = 0; j < 8; j++) {
                o[j][0] *= al0; o[j][1] *= al0;
                o[j][2] *= al1; o[j][3] *= al1;
            }

            uint32_t pf[4][4];
#pragma unroll
            for (int t = 0; t < 4; t++) {
                pf[t][0] = pack_h2(s[2*t][0],   s[2*t][1]);
                pf[t][1] = pack_h2(s[2*t][2],   s[2*t][3]);
                pf[t][2] = pack_h2(s[2*t+1][0], s[2*t+1][1]);
                pf[t][3] = pack_h2(s[2*t+1][2], s[2*t+1][3]);
            }
#pragma unroll
            for (int t = 0; t < 4; t++) {
#pragma unroll
                for (int j = 0; j < 8; j++) {
                    uint32_t vf[2];
                    ldsm_x2_t(vf, kvb + 18432u + vb_off + (uint32_t)(t * 16 * 144 + j * 16));
                    mma_f16(o[j], pf[t], vf);
                }
            }
        }

        __syncthreads();   // all readers of buf (nt&1) done before refill
        if (nt + 2 <= ntmax) {
            int kvn = (nt + 2) * 64;
            uint32_t kv = sb + KVs + (uint32_t)((nt & 1) * 27648);
#pragma unroll
            for (int i = 0; i < 6; i++) {
                int c = tid + i * 256;
                int t = c >> 9, idx = c & 511, row = idx >> 3, c16 = idx & 7;
                const void* src;
                if (t == 0)      src = KH + bhoff + (size_t)(kvn + row) * 64 + c16 * 8;
                else if (t == 1) src = KL + bhoff + (size_t)(kvn + row) * 64 + c16 * 8;
                else             src = VH + bhoff + (size_t)(kvn + row) * 64 + c16 * 8;
                CP_ASYNC16(kv + (uint32_t)(t * 9216 + row * 144 + c16 * 16), src);
            }
            CP_COMMIT();
        }
    }

    // epilogue: write bf16 hi/lo attention output
    int b_ = bh >> 4, h = bh & 15;
    float inv0 = 1.f / lrow0, inv1 = 1.f / lrow1;
#pragma unroll
    for (int rr = 0; rr < 2; rr++) {
        int row = q0w + (lane >> 2) + rr * 8;
        float inv = rr ? inv1 : inv0;
        size_t base = (size_t)(b_ * N_ + row) * D_ + h * 64;
#pragma unroll
        for (int j = 0; j < 8; j++) {
            int hd = 8 * j + ((lane & 3) << 1);
            float v0 = o[j][rr * 2 + 0] * inv;
            float v1 = o[j][rr * 2 + 1] * inv;
            __nv_bfloat162 hh = __floats2bfloat162_rn(v0, v1);
            float l0 = v0 - __low2float(hh), l1 = v1 - __high2float(hh);
            *reinterpret_cast<uint32_t*>(AHI + base + hd) = *reinterpret_cast<uint32_t*>(&hh);
            *reinterpret_cast<uint32_t*>(ALO + base + hd) = pack_bf2(l0, l1);
        }
    }
}

// ---------------------------------------------------------------------------
extern "C" void kernel_launch(void* const* d_in, const int* in_sizes, int n_in,
                              void* d_out, int out_size)
{
    const float* x      = (const float*)d_in[0];
    const float* qkv_w  = (const float*)d_in[1];
    const float* qkv_b  = (const float*)d_in[2];
    const float* proj_w = (const float*)d_in[3];
    const float* proj_b = (const float*)d_in[4];
    float* out = (float*)d_out;

    __nv_bfloat16 *xhi, *xlo, *wqh, *wql, *wph, *wpl, *ahi, *alo;
    __nv_bfloat16 *qh, *ql, *kh, *kl;
    __half *vh;
    cudaGetSymbolAddress((void**)&xhi, g_xhi);
    cudaGetSymbolAddress((void**)&xlo, g_xlo);
    cudaGetSymbolAddress((void**)&wqh, g_wqh);
    cudaGetSymbolAddress((void**)&wql, g_wql);
    cudaGetSymbolAddress((void**)&wph, g_wph);
    cudaGetSymbolAddress((void**)&wpl, g_wpl);
    cudaGetSymbolAddress((void**)&ahi, g_ahi);
    cudaGetSymbolAddress((void**)&alo, g_alo);
    cudaGetSymbolAddress((void**)&qh,  g_qh);
    cudaGetSymbolAddress((void**)&ql,  g_ql);
    cudaGetSymbolAddress((void**)&kh,  g_kh);
    cudaGetSymbolAddress((void**)&kl,  g_kl);
    cudaGetSymbolAddress((void**)&vh,  g_vh);

    const int GEMM_SMEM  = 81920;
    const int FLASH_SMEM = 92160;
    cudaFuncSetAttribute(mma_gemm_kernel,  cudaFuncAttributeMaxDynamicSharedMemorySize, GEMM_SMEM);
    cudaFuncSetAttribute(flash_mma_kernel, cudaFuncAttributeMaxDynamicSharedMemorySize, FLASH_SMEM);

    rope_table_kernel<<<(N_ * 32 + 255) / 256, 256>>>();

    {
        int n4 = 4096 * 1024 / 4;
        cvt_hilo_kernel<<<(n4 + 255) / 256, 256>>>((const float4*)x, (uint2*)xhi, (uint2*)xlo, n4);
    }
    {
        int n4 = 3072 * 1024 / 4;
        cvt_hilo_kernel<<<(n4 + 255) / 256, 256>>>((const float4*)qkv_w, (uint2*)wqh, (uint2*)wql, n4);
    }
    {
        int n4 = 1024 * 1024 / 4;
        cvt_hilo_kernel<<<(n4 + 255) / 256, 256>>>((const float4*)proj_w, (uint2*)wph, (uint2*)wpl, n4);
    }

    {   // QKV GEMM: M=4096, NC=3072
        dim3 grid(3072 / 128, 4096 / 128);
        mma_gemm_kernel<<<grid, 256, GEMM_SMEM>>>(xhi, xlo, wqh, wql, qkv_b,
                                                  qh, ql, kh, kl, vh, nullptr, 1);
    }
    {   // flash attention -> ahi/alo
        dim3 grid(N_ / 128, B_ * H_);
        flash_mma_kernel<<<grid, 256, FLASH_SMEM>>>(qh, ql, kh, kl, vh, ahi, alo);
    }
    {   // proj GEMM: M=4096, NC=1024
        dim3 grid(1024 / 128, 4096 / 128);
        mma_gemm_kernel<<<grid, 256, GEMM_SMEM>>>(ahi, alo, wph, wpl, proj_b,
                                                  nullptr, nullptr, nullptr, nullptr, nullptr, out, 0);
    }
}

// round 11
// speedup vs baseline: 3.3901x; 1.0068x over previous
#include <cuda_runtime.h>
#include <cuda_bf16.h>
#include <cuda_fp16.h>
#include <math.h>
#include <stdint.h>

#define B_  2
#define N_  2048
#define D_  1024
#define H_  16
#define HD_ 64

// bf16/fp16 operand arrays
__device__ __nv_bfloat16 g_xhi[4096*1024], g_xlo[4096*1024];
__device__ __nv_bfloat16 g_wqh[3072*1024], g_wql[3072*1024];
__device__ __nv_bfloat16 g_wph[1024*1024], g_wpl[1024*1024];
__device__ __nv_bfloat16 g_qh[32*2048*64], g_ql[32*2048*64];
__device__ __nv_bfloat16 g_kh[32*2048*64], g_kl[32*2048*64];
__device__ __half        g_vh[32*2048*64];
__device__ __nv_bfloat16 g_ahi[4096*1024], g_alo[4096*1024];
__device__ float g_cos[N_*32];
__device__ float g_sin[N_*32];

// ---------------------------------------------------------------------------
// helpers (sm_80+ target-agnostic PTX only)
// ---------------------------------------------------------------------------
__device__ __forceinline__ uint32_t smem_u32(const void* p) {
    uint32_t a;
    asm("{ .reg .u64 t; cvta.to.shared.u64 t, %1; cvt.u32.u64 %0, t; }" : "=r"(a) : "l"(p));
    return a;
}
__device__ __forceinline__ void ldsm_x4(uint32_t* r, uint32_t addr) {
    asm volatile("ldmatrix.sync.aligned.m8n8.x4.shared.b16 {%0,%1,%2,%3}, [%4];"
        : "=r"(r[0]), "=r"(r[1]), "=r"(r[2]), "=r"(r[3]) : "r"(addr));
}
__device__ __forceinline__ void ldsm_x2(uint32_t* r, uint32_t addr) {
    asm volatile("ldmatrix.sync.aligned.m8n8.x2.shared.b16 {%0,%1}, [%2];"
        : "=r"(r[0]), "=r"(r[1]) : "r"(addr));
}
__device__ __forceinline__ void ldsm_x2_t(uint32_t* r, uint32_t addr) {
    asm volatile("ldmatrix.sync.aligned.m8n8.x2.trans.shared.b16 {%0,%1}, [%2];"
        : "=r"(r[0]), "=r"(r[1]) : "r"(addr));
}
__device__ __forceinline__ void mma_bf16(float* c, const uint32_t* a, const uint32_t* b) {
    asm volatile(
        "mma.sync.aligned.m16n8k16.row.col.f32.bf16.bf16.f32 "
        "{%0,%1,%2,%3}, {%4,%5,%6,%7}, {%8,%9}, {%0,%1,%2,%3};"
        : "+f"(c[0]), "+f"(c[1]), "+f"(c[2]), "+f"(c[3])
        : "r"(a[0]), "r"(a[1]), "r"(a[2]), "r"(a[3]), "r"(b[0]), "r"(b[1]));
}
__device__ __forceinline__ void mma_f16(float* c, const uint32_t* a, const uint32_t* b) {
    asm volatile(
        "mma.sync.aligned.m16n8k16.row.col.f32.f16.f16.f32 "
        "{%0,%1,%2,%3}, {%4,%5,%6,%7}, {%8,%9}, {%0,%1,%2,%3};"
        : "+f"(c[0]), "+f"(c[1]), "+f"(c[2]), "+f"(c[3])
        : "r"(a[0]), "r"(a[1]), "r"(a[2]), "r"(a[3]), "r"(b[0]), "r"(b[1]));
}
#define CP_ASYNC16(dst, src) \
    asm volatile("cp.async.cg.shared.global [%0], [%1], 16;" :: "r"(dst), "l"(src))
#define CP_COMMIT() asm volatile("cp.async.commit_group;" ::: "memory")
#define CP_WAIT0()  asm volatile("cp.async.wait_group 0;" ::: "memory")
#define CP_WAIT1()  asm volatile("cp.async.wait_group 1;" ::: "memory")

__device__ __forceinline__ uint32_t pack_h2(float a, float b) {
    __half2 h = __floats2half2_rn(a, b);
    return *reinterpret_cast<uint32_t*>(&h);
}
__device__ __forceinline__ uint32_t pack_bf2(float a, float b) {
    __nv_bfloat162 h = __floats2bfloat162_rn(a, b);
    return *reinterpret_cast<uint32_t*>(&h);
}

// ---------------------------------------------------------------------------
__global__ void rope_table_kernel() {
    int idx = blockIdx.x * blockDim.x + threadIdx.x;
    if (idx >= N_ * 32) return;
    int n = idx >> 5;
    int p = idx & 31;
    float invf = (float)pow(10000.0, -(double)(2 * p) / (double)HD_);
    double ang = (double)((float)n * invf);
    g_cos[idx] = (float)cos(ang);
    g_sin[idx] = (float)sin(ang);
}

// Merged hi/lo converter for x (1M f4), qkv_w (768K f4), proj_w (256K f4).
__global__ void cvt_all_kernel(const float4* __restrict__ sx,
                               const float4* __restrict__ sq,
                               const float4* __restrict__ sp,
                               uint2* __restrict__ xh, uint2* __restrict__ xl,
                               uint2* __restrict__ qh, uint2* __restrict__ ql,
                               uint2* __restrict__ ph, uint2* __restrict__ pl) {
    int i = blockIdx.x * blockDim.x + threadIdx.x;   // [0, 2097152)
    const float4* src;
    uint2 *hi, *lo;
    int k;
    if (i < 1048576)       { src = sx; hi = xh; lo = xl; k = i; }
    else if (i < 1835008)  { src = sq; hi = qh; lo = ql; k = i - 1048576; }
    else                   { src = sp; hi = ph; lo = pl; k = i - 1835008; }
    float4 v = src[k];
    __nv_bfloat162 h01 = __floats2bfloat162_rn(v.x, v.y);
    __nv_bfloat162 h23 = __floats2bfloat162_rn(v.z, v.w);
    float r0 = v.x - __low2float(h01), r1 = v.y - __high2float(h01);
    float r2 = v.z - __low2float(h23), r3 = v.w - __high2float(h23);
    __nv_bfloat162 l01 = __floats2bfloat162_rn(r0, r1);
    __nv_bfloat162 l23 = __floats2bfloat162_rn(r2, r3);
    uint2 hw, lw;
    hw.x = *reinterpret_cast<const unsigned*>(&h01);
    hw.y = *reinterpret_cast<const unsigned*>(&h23);
    lw.x = *reinterpret_cast<const unsigned*>(&l01);
    lw.y = *reinterpret_cast<const unsigned*>(&l23);
    hi[k] = hw;
    lo[k] = lw;
}

// ---------------------------------------------------------------------------
// Single-pass 3-term GEMM (unchanged from R9/R10 passing version).
// ---------------------------------------------------------------------------
__global__ void __launch_bounds__(256, 2)
mma_gemm_kernel(const __nv_bfloat16* __restrict__ Ah, const __nv_bfloat16* __restrict__ Al,
                const __nv_bfloat16* __restrict__ Wh, const __nv_bfloat16* __restrict__ Wl,
                const float* __restrict__ bias,
                __nv_bfloat16* __restrict__ QH, __nv_bfloat16* __restrict__ QL,
                __nv_bfloat16* __restrict__ KH, __nv_bfloat16* __restrict__ KL,
                __half* __restrict__ VH, float* __restrict__ OUT, int qkv)
{
    extern __shared__ char sm[];
    uint32_t sb = smem_u32(sm);

    int tid = threadIdx.x;
    int lane = tid & 31;
    int wid = tid >> 5;
    int warp_m = wid & 1;
    int warp_n = wid >> 1;
    int n0 = blockIdx.x * 128, m0 = blockIdx.y * 128;

    uint32_t a_off = (uint32_t)((warp_m * 64 + (lane & 15)) * 80 + ((lane >> 4) << 4));
    uint32_t b_off = (uint32_t)((warp_n * 32 + (lane & 7)) * 80 + (((lane >> 3) & 1) << 4));

    float acc[4][4][4];
#pragma unroll
    for (int i = 0; i < 4; i++)
#pragma unroll
        for (int j = 0; j < 4; j++)
#pragma unroll
            for (int q = 0; q < 4; q++) acc[i][j][q] = 0.f;

    const __nv_bfloat16* srcs[4];
    srcs[0] = Ah + (size_t)m0 * 1024;
    srcs[1] = Al + (size_t)m0 * 1024;
    srcs[2] = Wh + (size_t)n0 * 1024;
    srcs[3] = Wl + (size_t)n0 * 1024;

#pragma unroll
    for (int i = 0; i < 8; i++) {
        int c = tid + i * 256;
        int t = c >> 9, idx = c & 511, row = idx >> 2, c16 = idx & 3;
        CP_ASYNC16(sb + (uint32_t)(t * 10240 + row * 80 + c16 * 16),
                   srcs[t] + (size_t)row * 1024 + c16 * 8);
    }
    CP_COMMIT();

    int buf = 0;
#pragma unroll 1
    for (int ck = 0; ck < 32; ck++) {
        if (ck < 31) {
            int ce = (ck + 1) * 32;
            uint32_t db = sb + (uint32_t)((buf ^ 1) * 40960);
#pragma unroll
            for (int i = 0; i < 8; i++) {
                int c = tid + i * 256;
                int t = c >> 9, idx = c & 511, row = idx >> 2, c16 = idx & 3;
                CP_ASYNC16(db + (uint32_t)(t * 10240 + row * 80 + c16 * 16),
                           srcs[t] + (size_t)row * 1024 + ce + c16 * 8);
            }
            CP_COMMIT();
            CP_WAIT1();
        } else {
            CP_WAIT0();
        }
        __syncthreads();

        uint32_t base = sb + (uint32_t)(buf * 40960);
#pragma unroll
        for (int kk = 0; kk < 2; kk++) {
            uint32_t aFh[4][4], aFl[4][4];
#pragma unroll
            for (int i = 0; i < 4; i++) {
                ldsm_x4(aFh[i], base + a_off + (uint32_t)(i * 16 * 80 + kk * 32));
                ldsm_x4(aFl[i], base + 10240u + a_off + (uint32_t)(i * 16 * 80 + kk * 32));
            }
#pragma unroll
            for (int j = 0; j < 4; j++) {
                uint32_t bh2[2], bl2[2];
                ldsm_x2(bh2, base + 20480u + b_off + (uint32_t)(j * 8 * 80 + kk * 32));
                ldsm_x2(bl2, base + 30720u + b_off + (uint32_t)(j * 8 * 80 + kk * 32));
#pragma unroll
                for (int i = 0; i < 4; i++) {
                    mma_bf16(acc[i][j], aFh[i], bh2);
                    mma_bf16(acc[i][j], aFh[i], bl2);
                    mma_bf16(acc[i][j], aFl[i], bh2);
                }
            }
        }
        __syncthreads();
        buf ^= 1;
    }

    // ---- epilogue ----
    int qrow = lane >> 2;
    int qcol = (lane & 3) << 1;
    int region = (qkv != 0) ? (n0 >> 10) : 0;

#pragma unroll
    for (int i = 0; i < 4; i++) {
#pragma unroll
        for (int hf = 0; hf < 2; hf++) {
            int m = m0 + warp_m * 64 + i * 16 + qrow + hf * 8;
            int bidx = m >> 11;
            int nrow = m & 2047;
#pragma unroll
            for (int j = 0; j < 4; j++) {
                int n = n0 + warp_n * 32 + j * 8 + qcol;
                float v0 = acc[i][j][hf * 2 + 0] + bias[n];
                float v1 = acc[i][j][hf * 2 + 1] + bias[n + 1];
                if (qkv == 0) {
                    *(float2*)(OUT + (size_t)m * 1024 + n) = make_float2(v0, v1);
                } else {
                    int h = (n & 1023) >> 6;
                    int hd = n & 63;
                    size_t off = ((size_t)(bidx * H_ + h) * N_ + nrow) * HD_ + hd;
                    if (region == 2) {
                        *reinterpret_cast<uint32_t*>(VH + off) = pack_h2(v0, v1);
                    } else {
                        int p = hd >> 1;
                        float c = g_cos[nrow * 32 + p], s = g_sin[nrow * 32 + p];
                        float w0 = v0 * c - v1 * s;
                        float w1 = v1 * c + v0 * s;
                        if (region == 0) { w0 *= 0.125f; w1 *= 0.125f; }
                        __nv_bfloat162 hh = __floats2bfloat162_rn(w0, w1);
                        float l0 = w0 - __low2float(hh), l1 = w1 - __high2float(hh);
                        __nv_bfloat16* dh = (region == 0) ? QH : KH;
                        __nv_bfloat16* dl = (region == 0) ? QL : KL;
                        *reinterpret_cast<uint32_t*>(dh + off) =
                            *reinterpret_cast<uint32_t*>(&hh);
                        *reinterpret_cast<uint32_t*>(dl + off) = pack_bf2(l0, l1);
                    }
                }
            }
        }
    }
}

// ---------------------------------------------------------------------------
// Tensor-core causal flash attention, double-buffered K/V.
// __launch_bounds__(256,2): cap regs at 128 -> 2 CTAs/SM (smem 2x92160 fits).
// Heavy tiles scheduled first: mt = gridDim.x-1-blockIdx.x.
// ---------------------------------------------------------------------------
__global__ void __launch_bounds__(256, 2) flash_mma_kernel(
    const __nv_bfloat16* __restrict__ QH, const __nv_bfloat16* __restrict__ QL,
    const __nv_bfloat16* __restrict__ KH, const __nv_bfloat16* __restrict__ KL,
    const __half* __restrict__ VH,
    __nv_bfloat16* __restrict__ AHI, __nv_bfloat16* __restrict__ ALO)
{
    extern __shared__ char sm[];
    uint32_t sb = smem_u32(sm);
    const uint32_t QHs = 0, QLs = 18432, KVs = 36864;   // + buf*27648

    int tid = threadIdx.x;
    int lane = tid & 31;
    int w = tid >> 5;
    int mt = (int)gridDim.x - 1 - (int)blockIdx.x;   // heavy tiles first
    int bh = blockIdx.y;
    int m0 = mt * 128;
    size_t bhoff = (size_t)bh * N_ * HD_;
    int ntmax = 2 * mt + 1;

    // prologue group 0: Q (hi+lo) + KV tile 0
#pragma unroll
    for (int i = 0; i < 8; i++) {
        int c = tid + i * 256;
        int t = c >> 10, idx = c & 1023, row = idx >> 3, c16 = idx & 7;
        const __nv_bfloat16* src = (t ? QL : QH) + bhoff + (size_t)(m0 + row) * 64 + c16 * 8;
        CP_ASYNC16(sb + (t ? QLs : QHs) + (uint32_t)(row * 144 + c16 * 16), src);
    }
    {
        uint32_t kv = sb + KVs;
#pragma unroll
        for (int i = 0; i < 6; i++) {
            int c = tid + i * 256;
            int t = c >> 9, idx = c & 511, row = idx >> 3, c16 = idx & 7;
            const void* src;
            if (t == 0)      src = KH + bhoff + (size_t)row * 64 + c16 * 8;
            else if (t == 1) src = KL + bhoff + (size_t)row * 64 + c16 * 8;
            else             src = VH + bhoff + (size_t)row * 64 + c16 * 8;
            CP_ASYNC16(kv + (uint32_t)(t * 9216 + row * 144 + c16 * 16), src);
        }
    }
    CP_COMMIT();
    // prologue group 1: KV tile 1
    {
        uint32_t kv = sb + KVs + 27648u;
#pragma unroll
        for (int i = 0; i < 6; i++) {
            int c = tid + i * 256;
            int t = c >> 9, idx = c & 511, row = idx >> 3, c16 = idx & 7;
            const void* src;
            if (t == 0)      src = KH + bhoff + (size_t)(64 + row) * 64 + c16 * 8;
            else if (t == 1) src = KL + bhoff + (size_t)(64 + row) * 64 + c16 * 8;
            else             src = VH + bhoff + (size_t)(64 + row) * 64 + c16 * 8;
            CP_ASYNC16(kv + (uint32_t)(t * 9216 + row * 144 + c16 * 16), src);
        }
    }
    CP_COMMIT();

    float o[8][4];
#pragma unroll
    for (int j = 0; j < 8; j++)
#pragma unroll
        for (int q = 0; q < 4; q++) o[j][q] = 0.f;
    float mrow0 = -1e30f, mrow1 = -1e30f, lrow0 = 0.f, lrow1 = 0.f;

    int q0w = m0 + w * 16;
    uint32_t qh_base = sb + QHs + (uint32_t)((w * 16 + (lane & 15)) * 144 + ((lane >> 4) << 4));
    uint32_t ql_base = qh_base + (QLs - QHs);
    uint32_t kb_off = (uint32_t)((lane & 7) * 144 + (((lane >> 3) & 1) << 4));
    uint32_t vb_off = (uint32_t)((lane & 15) * 144);

#pragma unroll 1
    for (int nt = 0; nt <= ntmax; nt++) {
        int kv0 = nt * 64;
        if (nt < ntmax) { CP_WAIT1(); } else { CP_WAIT0(); }
        __syncthreads();

        uint32_t kvb = sb + KVs + (uint32_t)((nt & 1) * 27648);

        if (kv0 <= q0w + 15) {
            float s[8][4];
#pragma unroll
            for (int j = 0; j < 8; j++)
#pragma unroll
                for (int q = 0; q < 4; q++) s[j][q] = 0.f;

#pragma unroll
            for (int kt = 0; kt < 4; kt++) {
                uint32_t ah[4], al[4];
                ldsm_x4(ah, qh_base + (uint32_t)(kt * 32));
                ldsm_x4(al, ql_base + (uint32_t)(kt * 32));
#pragma unroll
                for (int j = 0; j < 8; j++) {
                    uint32_t bh2[2], bl2[2];
                    ldsm_x2(bh2, kvb + kb_off + (uint32_t)(j * 8 * 144 + kt * 32));
                    ldsm_x2(bl2, kvb + 9216u + kb_off + (uint32_t)(j * 8 * 144 + kt * 32));
                    mma_bf16(s[j], ah, bh2);
                    mma_bf16(s[j], ah, bl2);
                    mma_bf16(s[j], al, bh2);
                }
            }

            if (kv0 + 63 > q0w) {
                int r0g = q0w + (lane >> 2);
                int r1g = r0g + 8;
#pragma unroll
                for (int j = 0; j < 8; j++) {
                    int cg = kv0 + 8 * j + ((lane & 3) << 1);
                    if (cg > r0g)     s[j][0] = -1e30f;
                    if (cg + 1 > r0g) s[j][1] = -1e30f;
                    if (cg > r1g)     s[j][2] = -1e30f;
                    if (cg + 1 > r1g) s[j][3] = -1e30f;
                }
            }

            float mx0 = -1e30f, mx1 = -1e30f;
#pragma unroll
            for (int j = 0; j < 8; j++) {
                mx0 = fmaxf(mx0, fmaxf(s[j][0], s[j][1]));
                mx1 = fmaxf(mx1, fmaxf(s[j][2], s[j][3]));
            }
            mx0 = fmaxf(mx0, __shfl_xor_sync(0xffffffffu, mx0, 1));
            mx0 = fmaxf(mx0, __shfl_xor_sync(0xffffffffu, mx0, 2));
            mx1 = fmaxf(mx1, __shfl_xor_sync(0xffffffffu, mx1, 1));
            mx1 = fmaxf(mx1, __shfl_xor_sync(0xffffffffu, mx1, 2));
            float mn0 = fmaxf(mrow0, mx0), mn1 = fmaxf(mrow1, mx1);
            float al0 = __expf(mrow0 - mn0), al1 = __expf(mrow1 - mn1);
            mrow0 = mn0; mrow1 = mn1;
            float rs0 = 0.f, rs1 = 0.f;
#pragma unroll
            for (int j = 0; j < 8; j++) {
                s[j][0] = __expf(s[j][0] - mn0);
                s[j][1] = __expf(s[j][1] - mn0);
                s[j][2] = __expf(s[j][2] - mn1);
                s[j][3] = __expf(s[j][3] - mn1);
                rs0 += s[j][0] + s[j][1];
                rs1 += s[j][2] + s[j][3];
            }
            rs0 += __shfl_xor_sync(0xffffffffu, rs0, 1);
            rs0 += __shfl_xor_sync(0xffffffffu, rs0, 2);
            rs1 += __shfl_xor_sync(0xffffffffu, rs1, 1);
            rs1 += __shfl_xor_sync(0xffffffffu, rs1, 2);
            lrow0 = lrow0 * al0 + rs0;
            lrow1 = lrow1 * al1 + rs1;
#pragma unroll
            for (int j = 0; j < 8; j++) {
                o[j][0] *= al0; o[j][1] *= al0;
                o[j][2] *= al1; o[j][3] *= al1;
            }

            uint32_t pf[4][4];
#pragma unroll
            for (int t = 0; t < 4; t++) {
                pf[t][0] = pack_h2(s[2*t][0],   s[2*t][1]);
                pf[t][1] = pack_h2(s[2*t][2],   s[2*t][3]);
                pf[t][2] = pack_h2(s[2*t+1][0], s[2*t+1][1]);
                pf[t][3] = pack_h2(s[2*t+1][2], s[2*t+1][3]);
            }
#pragma unroll
            for (int t = 0; t < 4; t++) {
#pragma unroll
                for (int j = 0; j < 8; j++) {
                    uint32_t vf[2];
                    ldsm_x2_t(vf, kvb + 18432u + vb_off + (uint32_t)(t * 16 * 144 + j * 16));
                    mma_f16(o[j], pf[t], vf);
                }
            }
        }

        __syncthreads();
        if (nt + 2 <= ntmax) {
            int kvn = (nt + 2) * 64;
            uint32_t kv = sb + KVs + (uint32_t)((nt & 1) * 27648);
#pragma unroll
            for (int i = 0; i < 6; i++) {
                int c = tid + i * 256;
                int t = c >> 9, idx = c & 511, row = idx >> 3, c16 = idx & 7;
                const void* src;
                if (t == 0)      src = KH + bhoff + (size_t)(kvn + row) * 64 + c16 * 8;
                else if (t == 1) src = KL + bhoff + (size_t)(kvn + row) * 64 + c16 * 8;
                else             src = VH + bhoff + (size_t)(kvn + row) * 64 + c16 * 8;
                CP_ASYNC16(kv + (uint32_t)(t * 9216 + row * 144 + c16 * 16), src);
            }
            CP_COMMIT();
        }
    }

    // epilogue: write bf16 hi/lo attention output
    int b_ = bh >> 4, h = bh & 15;
    float inv0 = 1.f / lrow0, inv1 = 1.f / lrow1;
#pragma unroll
    for (int rr = 0; rr < 2; rr++) {
        int row = q0w + (lane >> 2) + rr * 8;
        float inv = rr ? inv1 : inv0;
        size_t base = (size_t)(b_ * N_ + row) * D_ + h * 64;
#pragma unroll
        for (int j = 0; j < 8; j++) {
            int hd = 8 * j + ((lane & 3) << 1);
            float v0 = o[j][rr * 2 + 0] * inv;
            float v1 = o[j][rr * 2 + 1] * inv;
            __nv_bfloat162 hh = __floats2bfloat162_rn(v0, v1);
            float l0 = v0 - __low2float(hh), l1 = v1 - __high2float(hh);
            *reinterpret_cast<uint32_t*>(AHI + base + hd) = *reinterpret_cast<uint32_t*>(&hh);
            *reinterpret_cast<uint32_t*>(ALO + base + hd) = pack_bf2(l0, l1);
        }
    }
}

// ---------------------------------------------------------------------------
extern "C" void kernel_launch(void* const* d_in, const int* in_sizes, int n_in,
                              void* d_out, int out_size)
{
    const float* x      = (const float*)d_in[0];
    const float* qkv_w  = (const float*)d_in[1];
    const float* qkv_b  = (const float*)d_in[2];
    const float* proj_w = (const float*)d_in[3];
    const float* proj_b = (const float*)d_in[4];
    float* out = (float*)d_out;

    __nv_bfloat16 *xhi, *xlo, *wqh, *wql, *wph, *wpl, *ahi, *alo;
    __nv_bfloat16 *qh, *ql, *kh, *kl;
    __half *vh;
    cudaGetSymbolAddress((void**)&xhi, g_xhi);
    cudaGetSymbolAddress((void**)&xlo, g_xlo);
    cudaGetSymbolAddress((void**)&wqh, g_wqh);
    cudaGetSymbolAddress((void**)&wql, g_wql);
    cudaGetSymbolAddress((void**)&wph, g_wph);
    cudaGetSymbolAddress((void**)&wpl, g_wpl);
    cudaGetSymbolAddress((void**)&ahi, g_ahi);
    cudaGetSymbolAddress((void**)&alo, g_alo);
    cudaGetSymbolAddress((void**)&qh,  g_qh);
    cudaGetSymbolAddress((void**)&ql,  g_ql);
    cudaGetSymbolAddress((void**)&kh,  g_kh);
    cudaGetSymbolAddress((void**)&kl,  g_kl);
    cudaGetSymbolAddress((void**)&vh,  g_vh);

    const int GEMM_SMEM  = 81920;
    const int FLASH_SMEM = 92160;
    cudaFuncSetAttribute(mma_gemm_kernel,  cudaFuncAttributeMaxDynamicSharedMemorySize, GEMM_SMEM);
    cudaFuncSetAttribute(flash_mma_kernel, cudaFuncAttributeMaxDynamicSharedMemorySize, FLASH_SMEM);

    // 1: rope table
    rope_table_kernel<<<(N_ * 32 + 255) / 256, 256>>>();
    // 2: merged hi/lo conversion (x, qkv_w, proj_w)
    cvt_all_kernel<<<2097152 / 256, 256>>>((const float4*)x, (const float4*)qkv_w,
                                           (const float4*)proj_w,
                                           (uint2*)xhi, (uint2*)xlo,
                                           (uint2*)wqh, (uint2*)wql,
                                           (uint2*)wph, (uint2*)wpl);
    // 3: QKV GEMM
    {
        dim3 grid(3072 / 128, 4096 / 128);
        mma_gemm_kernel<<<grid, 256, GEMM_SMEM>>>(xhi, xlo, wqh, wql, qkv_b,
                                                  qh, ql, kh, kl, vh, nullptr, 1);
    }
    // 4: flash attention (profiled launch)
    {
        dim3 grid(N_ / 128, B_ * H_);
        flash_mma_kernel<<<grid, 256, FLASH_SMEM>>>(qh, ql, kh, kl, vh, ahi, alo);
    }
    // 5: proj GEMM
    {
        dim3 grid(1024 / 128, 4096 / 128);
        mma_gemm_kernel<<<grid, 256, GEMM_SMEM>>>(ahi, alo, wph, wpl, proj_b,
                                                  nullptr, nullptr, nullptr, nullptr, nullptr, out, 0);
    }
}

// round 12
// speedup vs baseline: 3.5620x; 1.0507x over previous
#include <cuda_runtime.h>
#include <cuda_bf16.h>
#include <cuda_fp16.h>
#include <math.h>
#include <stdint.h>

#define B_  2
#define N_  2048
#define D_  1024
#define H_  16
#define HD_ 64

// bf16/fp16 operand arrays
__device__ __nv_bfloat16 g_xhi[4096*1024], g_xlo[4096*1024];
__device__ __nv_bfloat16 g_wqh[3072*1024], g_wql[3072*1024];
__device__ __nv_bfloat16 g_wph[1024*1024], g_wpl[1024*1024];
__device__ __nv_bfloat16 g_qh[32*2048*64], g_ql[32*2048*64];
__device__ __nv_bfloat16 g_kh[32*2048*64], g_kl[32*2048*64];
__device__ __half        g_vh[32*2048*64];
__device__ __nv_bfloat16 g_ahi[4096*1024], g_alo[4096*1024];
__device__ float g_cos[N_*32];
__device__ float g_sin[N_*32];
// split-KV partials: 1024 slots = (bh*16+mt)*2+sp
__device__ float g_po[1024*8192];
__device__ float g_pm[1024*128];
__device__ float g_pl[1024*128];

// ---------------------------------------------------------------------------
// helpers (sm_80+ target-agnostic PTX only)
// ---------------------------------------------------------------------------
__device__ __forceinline__ uint32_t smem_u32(const void* p) {
    uint32_t a;
    asm("{ .reg .u64 t; cvta.to.shared.u64 t, %1; cvt.u32.u64 %0, t; }" : "=r"(a) : "l"(p));
    return a;
}
__device__ __forceinline__ void ldsm_x4(uint32_t* r, uint32_t addr) {
    asm volatile("ldmatrix.sync.aligned.m8n8.x4.shared.b16 {%0,%1,%2,%3}, [%4];"
        : "=r"(r[0]), "=r"(r[1]), "=r"(r[2]), "=r"(r[3]) : "r"(addr));
}
__device__ __forceinline__ void ldsm_x2(uint32_t* r, uint32_t addr) {
    asm volatile("ldmatrix.sync.aligned.m8n8.x2.shared.b16 {%0,%1}, [%2];"
        : "=r"(r[0]), "=r"(r[1]) : "r"(addr));
}
__device__ __forceinline__ void ldsm_x2_t(uint32_t* r, uint32_t addr) {
    asm volatile("ldmatrix.sync.aligned.m8n8.x2.trans.shared.b16 {%0,%1}, [%2];"
        : "=r"(r[0]), "=r"(r[1]) : "r"(addr));
}
__device__ __forceinline__ void mma_bf16(float* c, const uint32_t* a, const uint32_t* b) {
    asm volatile(
        "mma.sync.aligned.m16n8k16.row.col.f32.bf16.bf16.f32 "
        "{%0,%1,%2,%3}, {%4,%5,%6,%7}, {%8,%9}, {%0,%1,%2,%3};"
        : "+f"(c[0]), "+f"(c[1]), "+f"(c[2]), "+f"(c[3])
        : "r"(a[0]), "r"(a[1]), "r"(a[2]), "r"(a[3]), "r"(b[0]), "r"(b[1]));
}
__device__ __forceinline__ void mma_f16(float* c, const uint32_t* a, const uint32_t* b) {
    asm volatile(
        "mma.sync.aligned.m16n8k16.row.col.f32.f16.f16.f32 "
        "{%0,%1,%2,%3}, {%4,%5,%6,%7}, {%8,%9}, {%0,%1,%2,%3};"
        : "+f"(c[0]), "+f"(c[1]), "+f"(c[2]), "+f"(c[3])
        : "r"(a[0]), "r"(a[1]), "r"(a[2]), "r"(a[3]), "r"(b[0]), "r"(b[1]));
}
#define CP_ASYNC16(dst, src) \
    asm volatile("cp.async.cg.shared.global [%0], [%1], 16;" :: "r"(dst), "l"(src))
#define CP_COMMIT() asm volatile("cp.async.commit_group;" ::: "memory")
#define CP_WAIT0()  asm volatile("cp.async.wait_group 0;" ::: "memory")
#define CP_WAIT1()  asm volatile("cp.async.wait_group 1;" ::: "memory")

__device__ __forceinline__ uint32_t pack_h2(float a, float b) {
    __half2 h = __floats2half2_rn(a, b);
    return *reinterpret_cast<uint32_t*>(&h);
}
__device__ __forceinline__ uint32_t pack_bf2(float a, float b) {
    __nv_bfloat162 h = __floats2bfloat162_rn(a, b);
    return *reinterpret_cast<uint32_t*>(&h);
}

// ---------------------------------------------------------------------------
__global__ void rope_table_kernel() {
    int idx = blockIdx.x * blockDim.x + threadIdx.x;
    if (idx >= N_ * 32) return;
    int n = idx >> 5;
    int p = idx & 31;
    float invf = (float)pow(10000.0, -(double)(2 * p) / (double)HD_);
    double ang = (double)((float)n * invf);
    g_cos[idx] = (float)cos(ang);
    g_sin[idx] = (float)sin(ang);
}

// Merged hi/lo converter for x (1M f4), qkv_w (768K f4), proj_w (256K f4).
__global__ void cvt_all_kernel(const float4* __restrict__ sx,
                               const float4* __restrict__ sq,
                               const float4* __restrict__ sp,
                               uint2* __restrict__ xh, uint2* __restrict__ xl,
                               uint2* __restrict__ qh, uint2* __restrict__ ql,
                               uint2* __restrict__ ph, uint2* __restrict__ pl) {
    int i = blockIdx.x * blockDim.x + threadIdx.x;   // [0, 2097152)
    const float4* src;
    uint2 *hi, *lo;
    int k;
    if (i < 1048576)       { src = sx; hi = xh; lo = xl; k = i; }
    else if (i < 1835008)  { src = sq; hi = qh; lo = ql; k = i - 1048576; }
    else                   { src = sp; hi = ph; lo = pl; k = i - 1835008; }
    float4 v = src[k];
    __nv_bfloat162 h01 = __floats2bfloat162_rn(v.x, v.y);
    __nv_bfloat162 h23 = __floats2bfloat162_rn(v.z, v.w);
    float r0 = v.x - __low2float(h01), r1 = v.y - __high2float(h01);
    float r2 = v.z - __low2float(h23), r3 = v.w - __high2float(h23);
    __nv_bfloat162 l01 = __floats2bfloat162_rn(r0, r1);
    __nv_bfloat162 l23 = __floats2bfloat162_rn(r2, r3);
    uint2 hw, lw;
    hw.x = *reinterpret_cast<const unsigned*>(&h01);
    hw.y = *reinterpret_cast<const unsigned*>(&h23);
    lw.x = *reinterpret_cast<const unsigned*>(&l01);
    lw.y = *reinterpret_cast<const unsigned*>(&l23);
    hi[k] = hw;
    lo[k] = lw;
}

// ---------------------------------------------------------------------------
// Single-pass 3-term GEMM. 1 sync per chunk: wait -> sync -> issue -> compute.
// ---------------------------------------------------------------------------
__global__ void __launch_bounds__(256, 2)
mma_gemm_kernel(const __nv_bfloat16* __restrict__ Ah, const __nv_bfloat16* __restrict__ Al,
                const __nv_bfloat16* __restrict__ Wh, const __nv_bfloat16* __restrict__ Wl,
                const float* __restrict__ bias,
                __nv_bfloat16* __restrict__ QH, __nv_bfloat16* __restrict__ QL,
                __nv_bfloat16* __restrict__ KH, __nv_bfloat16* __restrict__ KL,
                __half* __restrict__ VH, float* __restrict__ OUT, int qkv)
{
    extern __shared__ char sm[];
    uint32_t sb = smem_u32(sm);

    int tid = threadIdx.x;
    int lane = tid & 31;
    int wid = tid >> 5;
    int warp_m = wid & 1;
    int warp_n = wid >> 1;
    int n0 = blockIdx.x * 128, m0 = blockIdx.y * 128;

    uint32_t a_off = (uint32_t)((warp_m * 64 + (lane & 15)) * 80 + ((lane >> 4) << 4));
    uint32_t b_off = (uint32_t)((warp_n * 32 + (lane & 7)) * 80 + (((lane >> 3) & 1) << 4));

    float acc[4][4][4];
#pragma unroll
    for (int i = 0; i < 4; i++)
#pragma unroll
        for (int j = 0; j < 4; j++)
#pragma unroll
            for (int q = 0; q < 4; q++) acc[i][j][q] = 0.f;

    const __nv_bfloat16* srcs[4];
    srcs[0] = Ah + (size_t)m0 * 1024;
    srcs[1] = Al + (size_t)m0 * 1024;
    srcs[2] = Wh + (size_t)n0 * 1024;
    srcs[3] = Wl + (size_t)n0 * 1024;

#pragma unroll
    for (int i = 0; i < 8; i++) {
        int c = tid + i * 256;
        int t = c >> 9, idx = c & 511, row = idx >> 2, c16 = idx & 3;
        CP_ASYNC16(sb + (uint32_t)(t * 10240 + row * 80 + c16 * 16),
                   srcs[t] + (size_t)row * 1024 + c16 * 8);
    }
    CP_COMMIT();

#pragma unroll 1
    for (int ck = 0; ck < 32; ck++) {
        int buf = ck & 1;
        CP_WAIT0();
        __syncthreads();           // chunk ck visible; reads of buf^1 (ck-1) done
        if (ck < 31) {             // issue ck+1 into buf^1 (safe: fenced above)
            int ce = (ck + 1) * 32;
            uint32_t db = sb + (uint32_t)((buf ^ 1) * 40960);
#pragma unroll
            for (int i = 0; i < 8; i++) {
                int c = tid + i * 256;
                int t = c >> 9, idx = c & 511, row = idx >> 2, c16 = idx & 3;
                CP_ASYNC16(db + (uint32_t)(t * 10240 + row * 80 + c16 * 16),
                           srcs[t] + (size_t)row * 1024 + ce + c16 * 8);
            }
            CP_COMMIT();
        }

        uint32_t base = sb + (uint32_t)(buf * 40960);
#pragma unroll
        for (int kk = 0; kk < 2; kk++) {
            uint32_t aFh[4][4], aFl[4][4];
#pragma unroll
            for (int i = 0; i < 4; i++) {
                ldsm_x4(aFh[i], base + a_off + (uint32_t)(i * 16 * 80 + kk * 32));
                ldsm_x4(aFl[i], base + 10240u + a_off + (uint32_t)(i * 16 * 80 + kk * 32));
            }
#pragma unroll
            for (int j = 0; j < 4; j++) {
                uint32_t bh2[2], bl2[2];
                ldsm_x2(bh2, base + 20480u + b_off + (uint32_t)(j * 8 * 80 + kk * 32));
                ldsm_x2(bl2, base + 30720u + b_off + (uint32_t)(j * 8 * 80 + kk * 32));
#pragma unroll
                for (int i = 0; i < 4; i++) {
                    mma_bf16(acc[i][j], aFh[i], bh2);
                    mma_bf16(acc[i][j], aFh[i], bl2);
                    mma_bf16(acc[i][j], aFl[i], bh2);
                }
            }
        }
    }

    // ---- epilogue ----
    int qrow = lane >> 2;
    int qcol = (lane & 3) << 1;
    int region = (qkv != 0) ? (n0 >> 10) : 0;

#pragma unroll
    for (int i = 0; i < 4; i++) {
#pragma unroll
        for (int hf = 0; hf < 2; hf++) {
            int m = m0 + warp_m * 64 + i * 16 + qrow + hf * 8;
            int bidx = m >> 11;
            int nrow = m & 2047;
#pragma unroll
            for (int j = 0; j < 4; j++) {
                int n = n0 + warp_n * 32 + j * 8 + qcol;
                float v0 = acc[i][j][hf * 2 + 0] + bias[n];
                float v1 = acc[i][j][hf * 2 + 1] + bias[n + 1];
                if (qkv == 0) {
                    *(float2*)(OUT + (size_t)m * 1024 + n) = make_float2(v0, v1);
                } else {
                    int h = (n & 1023) >> 6;
                    int hd = n & 63;
                    size_t off = ((size_t)(bidx * H_ + h) * N_ + nrow) * HD_ + hd;
                    if (region == 2) {
                        *reinterpret_cast<uint32_t*>(VH + off) = pack_h2(v0, v1);
                    } else {
                        int p = hd >> 1;
                        float c = g_cos[nrow * 32 + p], s = g_sin[nrow * 32 + p];
                        float w0 = v0 * c - v1 * s;
                        float w1 = v1 * c + v0 * s;
                        if (region == 0) { w0 *= 0.125f; w1 *= 0.125f; }
                        __nv_bfloat162 hh = __floats2bfloat162_rn(w0, w1);
                        float l0 = w0 - __low2float(hh), l1 = w1 - __high2float(hh);
                        __nv_bfloat16* dh = (region == 0) ? QH : KH;
                        __nv_bfloat16* dl = (region == 0) ? QL : KL;
                        *reinterpret_cast<uint32_t*>(dh + off) =
                            *reinterpret_cast<uint32_t*>(&hh);
                        *reinterpret_cast<uint32_t*>(dl + off) = pack_bf2(l0, l1);
                    }
                }
            }
        }
    }
}

// ---------------------------------------------------------------------------
// Split-KV tensor-core flash attention. grid (32, 32):
//   sidx = blockIdx.x; mt = 15 - (sidx>>1); sp = sidx&1 (heavy tiles first).
// Each CTA covers KV tiles [sp*(mt+1), (sp+1)*(mt+1)) and writes unnormalized
// partials (o, m, l) to scratch; merge_kernel combines the two halves.
// ---------------------------------------------------------------------------
__global__ void __launch_bounds__(256, 2) flash_mma_kernel(
    const __nv_bfloat16* __restrict__ QH, const __nv_bfloat16* __restrict__ QL,
    const __nv_bfloat16* __restrict__ KH, const __nv_bfloat16* __restrict__ KL,
    const __half* __restrict__ VH,
    float* __restrict__ PO, float* __restrict__ PM, float* __restrict__ PL)
{
    extern __shared__ char sm[];
    uint32_t sb = smem_u32(sm);
    const uint32_t QHs = 0, QLs = 18432, KVs = 36864;   // + buf*27648

    int tid = threadIdx.x;
    int lane = tid & 31;
    int w = tid >> 5;
    int sidx = blockIdx.x;
    int sp = sidx & 1;
    int mt = 15 - (sidx >> 1);
    int bh = blockIdx.y;
    int m0 = mt * 128;
    size_t bhoff = (size_t)bh * N_ * HD_;
    int half = mt + 1;
    int nt0 = sp * half;
    int nt_last = nt0 + half - 1;
    int slot = (bh * 16 + mt) * 2 + sp;

    // prologue group 0: Q (hi+lo) + KV tile nt0
#pragma unroll
    for (int i = 0; i < 8; i++) {
        int c = tid + i * 256;
        int t = c >> 10, idx = c & 1023, row = idx >> 3, c16 = idx & 7;
        const __nv_bfloat16* src = (t ? QL : QH) + bhoff + (size_t)(m0 + row) * 64 + c16 * 8;
        CP_ASYNC16(sb + (t ? QLs : QHs) + (uint32_t)(row * 144 + c16 * 16), src);
    }
    {
        int kv0 = nt0 * 64;
        uint32_t kv = sb + KVs;
#pragma unroll
        for (int i = 0; i < 6; i++) {
            int c = tid + i * 256;
            int t = c >> 9, idx = c & 511, row = idx >> 3, c16 = idx & 7;
            const void* src;
            if (t == 0)      src = KH + bhoff + (size_t)(kv0 + row) * 64 + c16 * 8;
            else if (t == 1) src = KL + bhoff + (size_t)(kv0 + row) * 64 + c16 * 8;
            else             src = VH + bhoff + (size_t)(kv0 + row) * 64 + c16 * 8;
            CP_ASYNC16(kv + (uint32_t)(t * 9216 + row * 144 + c16 * 16), src);
        }
    }
    CP_COMMIT();
    // prologue group 1: KV tile nt0+1 (always within global bounds; unused if half==1)
    {
        int kv0 = (nt0 + 1) * 64;
        if (kv0 >= N_) kv0 = 0;   // clamp (never computed in that case)
        uint32_t kv = sb + KVs + 27648u;
#pragma unroll
        for (int i = 0; i < 6; i++) {
            int c = tid + i * 256;
            int t = c >> 9, idx = c & 511, row = idx >> 3, c16 = idx & 7;
            const void* src;
            if (t == 0)      src = KH + bhoff + (size_t)(kv0 + row) * 64 + c16 * 8;
            else if (t == 1) src = KL + bhoff + (size_t)(kv0 + row) * 64 + c16 * 8;
            else             src = VH + bhoff + (size_t)(kv0 + row) * 64 + c16 * 8;
            CP_ASYNC16(kv + (uint32_t)(t * 9216 + row * 144 + c16 * 16), src);
        }
    }
    CP_COMMIT();

    float o[8][4];
#pragma unroll
    for (int j = 0; j < 8; j++)
#pragma unroll
        for (int q = 0; q < 4; q++) o[j][q] = 0.f;
    float mrow0 = -1e30f, mrow1 = -1e30f, lrow0 = 0.f, lrow1 = 0.f;

    int q0w = m0 + w * 16;
    uint32_t qh_base = sb + QHs + (uint32_t)((w * 16 + (lane & 15)) * 144 + ((lane >> 4) << 4));
    uint32_t ql_base = qh_base + (QLs - QHs);
    uint32_t kb_off = (uint32_t)((lane & 7) * 144 + (((lane >> 3) & 1) << 4));
    uint32_t vb_off = (uint32_t)((lane & 15) * 144);

#pragma unroll 1
    for (int nt = nt0; nt <= nt_last; nt++) {
        int it = nt - nt0;
        int kv0 = nt * 64;
        if (nt < nt_last) { CP_WAIT1(); } else { CP_WAIT0(); }
        __syncthreads();

        uint32_t kvb = sb + KVs + (uint32_t)((it & 1) * 27648);

        if (kv0 <= q0w + 15) {
            float s[8][4];
#pragma unroll
            for (int j = 0; j < 8; j++)
#pragma unroll
                for (int q = 0; q < 4; q++) s[j][q] = 0.f;

#pragma unroll
            for (int kt = 0; kt < 4; kt++) {
                uint32_t ah[4], al[4];
                ldsm_x4(ah, qh_base + (uint32_t)(kt * 32));
                ldsm_x4(al, ql_base + (uint32_t)(kt * 32));
#pragma unroll
                for (int j = 0; j < 8; j++) {
                    uint32_t bh2[2], bl2[2];
                    ldsm_x2(bh2, kvb + kb_off + (uint32_t)(j * 8 * 144 + kt * 32));
                    ldsm_x2(bl2, kvb + 9216u + kb_off + (uint32_t)(j * 8 * 144 + kt * 32));
                    mma_bf16(s[j], ah, bh2);
                    mma_bf16(s[j], ah, bl2);
                    mma_bf16(s[j], al, bh2);
                }
            }

            if (kv0 + 63 > q0w) {
                int r0g = q0w + (lane >> 2);
                int r1g = r0g + 8;
#pragma unroll
                for (int j = 0; j < 8; j++) {
                    int cg = kv0 + 8 * j + ((lane & 3) << 1);
                    if (cg > r0g)     s[j][0] = -1e30f;
                    if (cg + 1 > r0g) s[j][1] = -1e30f;
                    if (cg > r1g)     s[j][2] = -1e30f;
                    if (cg + 1 > r1g) s[j][3] = -1e30f;
                }
            }

            float mx0 = -1e30f, mx1 = -1e30f;
#pragma unroll
            for (int j = 0; j < 8; j++) {
                mx0 = fmaxf(mx0, fmaxf(s[j][0], s[j][1]));
                mx1 = fmaxf(mx1, fmaxf(s[j][2], s[j][3]));
            }
            mx0 = fmaxf(mx0, __shfl_xor_sync(0xffffffffu, mx0, 1));
            mx0 = fmaxf(mx0, __shfl_xor_sync(0xffffffffu, mx0, 2));
            mx1 = fmaxf(mx1, __shfl_xor_sync(0xffffffffu, mx1, 1));
            mx1 = fmaxf(mx1, __shfl_xor_sync(0xffffffffu, mx1, 2));
            float mn0 = fmaxf(mrow0, mx0), mn1 = fmaxf(mrow1, mx1);
            float al0 = __expf(mrow0 - mn0), al1 = __expf(mrow1 - mn1);
            mrow0 = mn0; mrow1 = mn1;
            float rs0 = 0.f, rs1 = 0.f;
#pragma unroll
            for (int j = 0; j < 8; j++) {
                s[j][0] = __expf(s[j][0] - mn0);
                s[j][1] = __expf(s[j][1] - mn0);
                s[j][2] = __expf(s[j][2] - mn1);
                s[j][3] = __expf(s[j][3] - mn1);
                rs0 += s[j][0] + s[j][1];
                rs1 += s[j][2] + s[j][3];
            }
            rs0 += __shfl_xor_sync(0xffffffffu, rs0, 1);
            rs0 += __shfl_xor_sync(0xffffffffu, rs0, 2);
            rs1 += __shfl_xor_sync(0xffffffffu, rs1, 1);
            rs1 += __shfl_xor_sync(0xffffffffu, rs1, 2);
            lrow0 = lrow0 * al0 + rs0;
            lrow1 = lrow1 * al1 + rs1;
#pragma unroll
            for (int j = 0; j < 8; j++) {
                o[j][0] *= al0; o[j][1] *= al0;
                o[j][2] *= al1; o[j][3] *= al1;
            }

            uint32_t pf[4][4];
#pragma unroll
            for (int t = 0; t < 4; t++) {
                pf[t][0] = pack_h2(s[2*t][0],   s[2*t][1]);
                pf[t][1] = pack_h2(s[2*t][2],   s[2*t][3]);
                pf[t][2] = pack_h2(s[2*t+1][0], s[2*t+1][1]);
                pf[t][3] = pack_h2(s[2*t+1][2], s[2*t+1][3]);
            }
#pragma unroll
            for (int t = 0; t < 4; t++) {
#pragma unroll
                for (int j = 0; j < 8; j++) {
                    uint32_t vf[2];
                    ldsm_x2_t(vf, kvb + 18432u + vb_off + (uint32_t)(t * 16 * 144 + j * 16));
                    mma_f16(o[j], pf[t], vf);
                }
            }
        }

        __syncthreads();
        if (nt + 2 <= nt_last) {
            int kvn = (nt + 2) * 64;
            uint32_t kv = sb + KVs + (uint32_t)((it & 1) * 27648);
#pragma unroll
            for (int i = 0; i < 6; i++) {
                int c = tid + i * 256;
                int t = c >> 9, idx = c & 511, row = idx >> 3, c16 = idx & 7;
                const void* src;
                if (t == 0)      src = KH + bhoff + (size_t)(kvn + row) * 64 + c16 * 8;
                else if (t == 1) src = KL + bhoff + (size_t)(kvn + row) * 64 + c16 * 8;
                else             src = VH + bhoff + (size_t)(kvn + row) * 64 + c16 * 8;
                CP_ASYNC16(kv + (uint32_t)(t * 9216 + row * 144 + c16 * 16), src);
            }
            CP_COMMIT();
        }
    }

    // epilogue: write unnormalized partials to scratch
    float* po = PO + (size_t)slot * 8192;
#pragma unroll
    for (int rr = 0; rr < 2; rr++) {
        int rl = w * 16 + (lane >> 2) + rr * 8;
#pragma unroll
        for (int j = 0; j < 8; j++) {
            int hd = 8 * j + ((lane & 3) << 1);
            *(float2*)(po + rl * 64 + hd) =
                make_float2(o[j][rr * 2 + 0], o[j][rr * 2 + 1]);
        }
        if ((lane & 3) == 0) {
            PM[slot * 128 + rl] = rr ? mrow1 : mrow0;
            PL[slot * 128 + rl] = rr ? lrow1 : lrow0;
        }
    }
}

// ---------------------------------------------------------------------------
// Merge split-KV partials -> bf16 hi/lo attention output.
// 524288 threads: row_id = gid>>3 (65536 rows), 8 dims each.
// ---------------------------------------------------------------------------
__global__ void merge_kernel(const float* __restrict__ PO,
                             const float* __restrict__ PM,
                             const float* __restrict__ PL,
                             __nv_bfloat16* __restrict__ AHI,
                             __nv_bfloat16* __restrict__ ALO)
{
    int gid = blockIdx.x * blockDim.x + threadIdx.x;
    int row_id = gid >> 3;
    int dp = (gid & 7) * 8;
    int bh = row_id >> 11;
    int rin = row_id & 2047;
    int mt = rin >> 7;
    int row = rin & 127;
    int slot0 = (bh * 16 + mt) * 2;

    float m0 = PM[slot0 * 128 + row],       m1 = PM[(slot0 + 1) * 128 + row];
    float l0 = PL[slot0 * 128 + row],       l1 = PL[(slot0 + 1) * 128 + row];
    float M = fmaxf(m0, m1);
    float w0 = __expf(m0 - M), w1 = __expf(m1 - M);
    float inv = 1.f / (l0 * w0 + l1 * w1);

    const float* p0 = PO + (size_t)slot0 * 8192 + row * 64 + dp;
    const float* p1 = p0 + 8192;
    int b_ = bh >> 4, h = bh & 15;
    int token = mt * 128 + row;
    size_t base = ((size_t)(b_ * N_ + token)) * D_ + h * 64 + dp;

#pragma unroll
    for (int i = 0; i < 8; i += 2) {
        float v0 = (p0[i] * w0 + p1[i] * w1) * inv;
        float v1 = (p0[i+1] * w0 + p1[i+1] * w1) * inv;
        __nv_bfloat162 hh = __floats2bfloat162_rn(v0, v1);
        float e0 = v0 - __low2float(hh), e1 = v1 - __high2float(hh);
        *reinterpret_cast<uint32_t*>(AHI + base + i) = *reinterpret_cast<uint32_t*>(&hh);
        *reinterpret_cast<uint32_t*>(ALO + base + i) = pack_bf2(e0, e1);
    }
}

// ---------------------------------------------------------------------------
extern "C" void kernel_launch(void* const* d_in, const int* in_sizes, int n_in,
                              void* d_out, int out_size)
{
    const float* x      = (const float*)d_in[0];
    const float* qkv_w  = (const float*)d_in[1];
    const float* qkv_b  = (const float*)d_in[2];
    const float* proj_w = (const float*)d_in[3];
    const float* proj_b = (const float*)d_in[4];
    float* out = (float*)d_out;

    __nv_bfloat16 *xhi, *xlo, *wqh, *wql, *wph, *wpl, *ahi, *alo;
    __nv_bfloat16 *qh, *ql, *kh, *kl;
    __half *vh;
    float *po, *pm, *pl;
    cudaGetSymbolAddress((void**)&xhi, g_xhi);
    cudaGetSymbolAddress((void**)&xlo, g_xlo);
    cudaGetSymbolAddress((void**)&wqh, g_wqh);
    cudaGetSymbolAddress((void**)&wql, g_wql);
    cudaGetSymbolAddress((void**)&wph, g_wph);
    cudaGetSymbolAddress((void**)&wpl, g_wpl);
    cudaGetSymbolAddress((void**)&ahi, g_ahi);
    cudaGetSymbolAddress((void**)&alo, g_alo);
    cudaGetSymbolAddress((void**)&qh,  g_qh);
    cudaGetSymbolAddress((void**)&ql,  g_ql);
    cudaGetSymbolAddress((void**)&kh,  g_kh);
    cudaGetSymbolAddress((void**)&kl,  g_kl);
    cudaGetSymbolAddress((void**)&vh,  g_vh);
    cudaGetSymbolAddress((void**)&po,  g_po);
    cudaGetSymbolAddress((void**)&pm,  g_pm);
    cudaGetSymbolAddress((void**)&pl,  g_pl);

    const int GEMM_SMEM  = 81920;
    const int FLASH_SMEM = 92160;
    cudaFuncSetAttribute(mma_gemm_kernel,  cudaFuncAttributeMaxDynamicSharedMemorySize, GEMM_SMEM);
    cudaFuncSetAttribute(flash_mma_kernel, cudaFuncAttributeMaxDynamicSharedMemorySize, FLASH_SMEM);

    // 1: rope table
    rope_table_kernel<<<(N_ * 32 + 255) / 256, 256>>>();
    // 2: merged hi/lo conversion
    cvt_all_kernel<<<2097152 / 256, 256>>>((const float4*)x, (const float4*)qkv_w,
                                           (const float4*)proj_w,
                                           (uint2*)xhi, (uint2*)xlo,
                                           (uint2*)wqh, (uint2*)wql,
                                           (uint2*)wph, (uint2*)wpl);
    // 3: QKV GEMM
    {
        dim3 grid(3072 / 128, 4096 / 128);
        mma_gemm_kernel<<<grid, 256, GEMM_SMEM>>>(xhi, xlo, wqh, wql, qkv_b,
                                                  qh, ql, kh, kl, vh, nullptr, 1);
    }
    // 4: split-KV flash attention (profiled launch)
    {
        dim3 grid(32, 32);
        flash_mma_kernel<<<grid, 256, FLASH_SMEM>>>(qh, ql, kh, kl, vh, po, pm, pl);
    }
    // 5: merge partials
    merge_kernel<<<524288 / 256, 256>>>(po, pm, pl, ahi, alo);
    // 6: proj GEMM
    {
        dim3 grid(1024 / 128, 4096 / 128);
        mma_gemm_kernel<<<grid, 256, GEMM_SMEM>>>(ahi, alo, wph, wpl, proj_b,
                                                  nullptr, nullptr, nullptr, nullptr, nullptr, out, 0);
    }
}